// round 4
// baseline (speedup 1.0000x reference)
#include <cuda_runtime.h>

#define NN 50000
#define TN 32
#define NTHREADS 256
#define HSTR 34

typedef unsigned long long u64;

__device__ __align__(256) float g_y[(size_t)NN * 512];
__device__ __align__(256) float g_WihT[128 * 512];
__device__ __align__(256) float g_WhhT[128 * 512];
__device__ __align__(256) float g_WselfT[128 * 128];
__device__ __align__(256) float g_WneighT[128 * 128];

__device__ __forceinline__ u64 pack2(float lo, float hi) {
    u64 r; asm("mov.b64 %0,{%1,%2};" : "=l"(r) : "f"(lo), "f"(hi)); return r;
}
__device__ __forceinline__ u64 pack2s(float v) { return pack2(v, v); }
__device__ __forceinline__ void unpack2(u64 v, float& lo, float& hi) {
    asm("mov.b64 {%0,%1},%2;" : "=f"(lo), "=f"(hi) : "l"(v));
}
__device__ __forceinline__ void ffma2(u64& d, u64 a, u64 b) {
    asm("fma.rn.f32x2 %0,%1,%2,%0;" : "+l"(d) : "l"(a), "l"(b));
}
__device__ __forceinline__ void cp16(float* dst, const float* src) {
    unsigned sa = (unsigned)__cvta_generic_to_shared(dst);
    asm volatile("cp.async.cg.shared.global [%0],[%1],16;" :: "r"(sa), "l"(src) : "memory");
}
__device__ __forceinline__ void cp_commit() { asm volatile("cp.async.commit_group;" ::: "memory"); }
template <int W> __device__ __forceinline__ void cp_wait() {
    asm volatile("cp.async.wait_group %0;" :: "n"(W) : "memory");
}
__device__ __forceinline__ void cp_chunk(float* dstS, const float* src, int tid) {
#pragma unroll
    for (int i = 0; i < 16; ++i) { int f4 = i * NTHREADS + tid; cp16(dstS + f4 * 4, src + f4 * 4); }
}
__device__ __forceinline__ float sigf(float v) { return __fdividef(1.f, 1.f + __expf(-v)); }
__device__ __forceinline__ float tanhf_fast(float v) { return 1.f - __fdividef(2.f, __expf(2.f * v) + 1.f); }

__device__ __forceinline__ void mma_chunk(const float* __restrict__ Wb, const float* __restrict__ act,
                                          u64* ai, u64* af, u64* ag, u64* ao, int j) {
#pragma unroll 8
    for (int kk = 0; kk < 32; ++kk) {
        const float* wr = Wb + kk * 512 + j;
        u64 wi = pack2s(wr[0]), wf = pack2s(wr[128]), wg = pack2s(wr[256]), wo = pack2s(wr[384]);
        const u64* hp = (const u64*)(act + kk * HSTR);
#pragma unroll
        for (int p = 0; p < 8; ++p) {
            u64 hv = hp[p];
            ffma2(ai[p], wi, hv); ffma2(af[p], wf, hv);
            ffma2(ag[p], wg, hv); ffma2(ao[p], wo, hv);
        }
    }
}

__device__ __forceinline__ void stage_x_tile(float* sm_x, const float* __restrict__ x, int base, int tid) {
    int node = tid >> 3, q = tid & 7, n = base + node;
#pragma unroll
    for (int u = 0; u < 4; ++u) {
        float4 v = make_float4(0.f, 0.f, 0.f, 0.f);
        if (n < NN) v = ((const float4*)(x + (size_t)n * 128))[q * 4 + u];
        int k0 = q * 16 + u * 4;
        sm_x[(k0 + 0) * HSTR + node] = v.x; sm_x[(k0 + 1) * HSTR + node] = v.y;
        sm_x[(k0 + 2) * HSTR + node] = v.z; sm_x[(k0 + 3) * HSTR + node] = v.w;
    }
}

__global__ void prep_kernel(const float* __restrict__ W_ih, const float* __restrict__ W_hh,
                            const float* __restrict__ W_self, const float* __restrict__ W_neigh) {
    int i = blockIdx.x * 256 + threadIdx.x;
    if (i < 512 * 128) {
        int g = i & 511, k = i >> 9;
        g_WihT[k * 512 + g] = W_ih[g * 128 + k];
        g_WhhT[k * 512 + g] = W_hh[g * 128 + k];
    }
    if (i < 128 * 128) {
        int jj = i & 127, k = i >> 7;
        g_WselfT[k * 128 + jj] = W_self[jj * 128 + k];
        g_WneighT[k * 128 + jj] = W_neigh[jj * 128 + k];
    }
}

// y = x @ W_ih^T + b_ih   (smem: buf0 | buf1 | sm_x)
__global__ __launch_bounds__(256, 1) void y_kernel(const float* __restrict__ x,
                                                   const float* __restrict__ b_ih) {
    extern __shared__ float smem[];
    float* buf[2] = { smem, smem + 16384 };
    float* sm_x = smem + 32768;
    const int tid = threadIdx.x, j = tid & 127, ng = tid >> 7, base = blockIdx.x * TN;

    cp_chunk(buf[0], g_WihT, tid); cp_commit();
    stage_x_tile(sm_x, x, base, tid);

    float bi = b_ih[j], bf = b_ih[128 + j], bg = b_ih[256 + j], bo = b_ih[384 + j];
    u64 ai[8], af[8], ag[8], ao[8];
#pragma unroll
    for (int p = 0; p < 8; ++p) { ai[p] = pack2s(bi); af[p] = pack2s(bf); ag[p] = pack2s(bg); ao[p] = pack2s(bo); }

    int cur = 0;
#pragma unroll 1
    for (int kc = 0; kc < 4; ++kc) {
        __syncthreads();
        if (kc < 3) { cp_chunk(buf[cur ^ 1], g_WihT + (kc + 1) * 16384, tid); cp_commit(); cp_wait<1>(); }
        else cp_wait<0>();
        __syncthreads();
        mma_chunk(buf[cur], sm_x + kc * 32 * HSTR + ng * 16, ai, af, ag, ao, j);
        cur ^= 1;
    }
#pragma unroll
    for (int p = 0; p < 8; ++p) {
        int n0 = base + ng * 16 + 2 * p, n1 = n0 + 1;
        float lo, hi;
        unpack2(ai[p], lo, hi); if (n0 < NN) g_y[(size_t)n0 * 512 + j] = lo;       if (n1 < NN) g_y[(size_t)n1 * 512 + j] = hi;
        unpack2(af[p], lo, hi); if (n0 < NN) g_y[(size_t)n0 * 512 + 128 + j] = lo; if (n1 < NN) g_y[(size_t)n1 * 512 + 128 + j] = hi;
        unpack2(ag[p], lo, hi); if (n0 < NN) g_y[(size_t)n0 * 512 + 256 + j] = lo; if (n1 < NN) g_y[(size_t)n1 * 512 + 256 + j] = hi;
        unpack2(ao[p], lo, hi); if (n0 < NN) g_y[(size_t)n0 * 512 + 384 + j] = lo; if (n1 < NN) g_y[(size_t)n1 * 512 + 384 + j] = hi;
    }
}

// smem floats: buf0[16384] buf1[16384] sm_h[4352] sm_x[4352] sm_r[4224] sm_idx[512]
#define OFF_H 32768
#define OFF_X 37120
#define OFF_R 41472
#define OFF_I 45696

__global__ __launch_bounds__(256, 1) void lstm_kernel(
    const float* __restrict__ x, const int* __restrict__ nidx,
    const float* __restrict__ b_hh, const float* __restrict__ b_self, const float* __restrict__ b_neigh,
    const float* __restrict__ g1, const float* __restrict__ bt1,
    const float* __restrict__ g3, const float* __restrict__ bt3,
    float* __restrict__ out) {
    extern __shared__ float smem[];
    float* buf[2] = { smem, smem + 16384 };
    float* sm_h = smem + OFF_H;
    float* sm_x = smem + OFF_X;
    float* sm_r = smem + OFF_R;
    int*   sm_idx = (int*)(smem + OFF_I);

    const int tid = threadIdx.x, j = tid & 127, ng = tid >> 7, base = blockIdx.x * TN;

    for (int i = tid; i < TN * 16; i += NTHREADS) {
        int n = base + (i >> 4);
        sm_idx[i] = (n < NN) ? nidx[n * 16 + (i & 15)] : 0;
    }

    float bi = b_hh[j], bf = b_hh[128 + j], bg = b_hh[256 + j], bo = b_hh[384 + j];
    float c[16];
#pragma unroll
    for (int i = 0; i < 16; ++i) c[i] = 0.f;
    u64 ai[8], af[8], ag[8], ao[8];
    __syncthreads();

#define INIT_ACC(T)                                                          \
    {                                                                        \
        _Pragma("unroll")                                                    \
        for (int p = 0; p < 8; ++p) {                                        \
            int l0 = ng * 16 + 2 * p;                                        \
            const float* y0 = g_y + (size_t)sm_idx[l0 * 16 + (T)] * 512 + j; \
            const float* y1 = g_y + (size_t)sm_idx[(l0 + 1) * 16 + (T)] * 512 + j; \
            ai[p] = pack2(y0[0] + bi,   y1[0] + bi);                         \
            af[p] = pack2(y0[128] + bf, y1[128] + bf);                       \
            ag[p] = pack2(y0[256] + bg, y1[256] + bg);                       \
            ao[p] = pack2(y0[384] + bo, y1[384] + bo);                       \
        }                                                                    \
    }

#define ACTIVATION()                                                         \
    {                                                                        \
        _Pragma("unroll")                                                    \
        for (int p = 0; p < 8; ++p) {                                        \
            float i0, i1, f0, f1, q0, q1, o0, o1;                            \
            unpack2(ai[p], i0, i1); unpack2(af[p], f0, f1);                  \
            unpack2(ag[p], q0, q1); unpack2(ao[p], o0, o1);                  \
            float c0 = sigf(f0) * c[2 * p]     + sigf(i0) * tanhf_fast(q0);  \
            float c1 = sigf(f1) * c[2 * p + 1] + sigf(i1) * tanhf_fast(q1);  \
            c[2 * p] = c0; c[2 * p + 1] = c1;                                \
            *(u64*)(sm_h + j * HSTR + ng * 16 + 2 * p) =                     \
                pack2(sigf(o0) * tanhf_fast(c0), sigf(o1) * tanhf_fast(c1)); \
        }                                                                    \
    }

    INIT_ACC(0);
    ACTIVATION();
    cp_chunk(buf[0], g_WhhT, tid); cp_commit();

    int cur = 0;
#pragma unroll 1
    for (int t = 1; t < 16; ++t) {
        INIT_ACC(t);
#pragma unroll 1
        for (int kc = 0; kc < 4; ++kc) {
            __syncthreads();
            const float* nsrc = (kc < 3) ? (g_WhhT + (kc + 1) * 16384)
                                         : ((t < 15) ? g_WhhT : g_WselfT);
            cp_chunk(buf[cur ^ 1], nsrc, tid); cp_commit();
            cp_wait<1>();
            __syncthreads();
            mma_chunk(buf[cur], sm_h + kc * 32 * HSTR + ng * 16, ai, af, ag, ao, j);
            cur ^= 1;
        }
        __syncthreads();   // all reads of sm_h / buf done before overwrite
        ACTIVATION();
    }
    // buf[0] <- W_selfT in flight (committed at t=15,kc=3); buf[1] free.
    cp_chunk(buf[1], g_WneighT, tid); cp_commit();
    stage_x_tile(sm_x, x, base, tid);
    cp_wait<0>();
    __syncthreads();   // buf0=WselfT, buf1=WneighT, sm_x staged, sm_h final visible

    // r = x@Wself^T + h@Wneigh^T + (b_self+b_neigh)
    float bsn = b_self[j] + b_neigh[j];
    u64 racc[8];
#pragma unroll
    for (int p = 0; p < 8; ++p) racc[p] = pack2s(bsn);
#pragma unroll 4
    for (int k = 0; k < 128; ++k) {
        u64 ws = pack2s(buf[0][k * 128 + j]);
        u64 wn = pack2s(buf[1][k * 128 + j]);
        const u64* xp = (const u64*)(sm_x + k * HSTR + ng * 16);
        const u64* hp = (const u64*)(sm_h + k * HSTR + ng * 16);
#pragma unroll
        for (int p = 0; p < 8; ++p) { ffma2(racc[p], ws, xp[p]); ffma2(racc[p], wn, hp[p]); }
    }
#pragma unroll
    for (int p = 0; p < 8; ++p) {
        float lo, hi; unpack2(racc[p], lo, hi);
        int node = ng * 16 + 2 * p;
        sm_r[node * 132 + j] = lo;
        sm_r[(node + 1) * 132 + j] = hi;
    }
    __syncthreads();

    // LN -> leaky -> +x -> LN -> leaky.  warp w handles nodes w*4..w*4+3
    int w = tid >> 5, l = tid & 31;
    float4 gv1 = *(const float4*)(g1 + l * 4), bv1 = *(const float4*)(bt1 + l * 4);
    float4 gv3 = *(const float4*)(g3 + l * 4), bv3 = *(const float4*)(bt3 + l * 4);
#pragma unroll 1
    for (int q = 0; q < 4; ++q) {
        int node = w * 4 + q, n = base + node;
        if (n >= NN) break;
        float4 rv = *(float4*)(sm_r + node * 132 + l * 4);
        float4 xv = *(const float4*)(x + (size_t)n * 128 + l * 4);
        float s1 = rv.x + rv.y + rv.z + rv.w;
        float s2 = rv.x * rv.x + rv.y * rv.y + rv.z * rv.z + rv.w * rv.w;
#pragma unroll
        for (int m = 16; m > 0; m >>= 1) { s1 += __shfl_xor_sync(~0u, s1, m); s2 += __shfl_xor_sync(~0u, s2, m); }
        float mu = s1 * 0.0078125f;
        float rs = rsqrtf(s2 * 0.0078125f - mu * mu + 1e-5f);
        float4 h;
        h.x = (rv.x - mu) * rs * gv1.x + bv1.x; h.y = (rv.y - mu) * rs * gv1.y + bv1.y;
        h.z = (rv.z - mu) * rs * gv1.z + bv1.z; h.w = (rv.w - mu) * rs * gv1.w + bv1.w;
        h.x = fmaxf(h.x, 0.01f * h.x) + xv.x; h.y = fmaxf(h.y, 0.01f * h.y) + xv.y;
        h.z = fmaxf(h.z, 0.01f * h.z) + xv.z; h.w = fmaxf(h.w, 0.01f * h.w) + xv.w;
        s1 = h.x + h.y + h.z + h.w;
        s2 = h.x * h.x + h.y * h.y + h.z * h.z + h.w * h.w;
#pragma unroll
        for (int m = 16; m > 0; m >>= 1) { s1 += __shfl_xor_sync(~0u, s1, m); s2 += __shfl_xor_sync(~0u, s2, m); }
        mu = s1 * 0.0078125f;
        rs = rsqrtf(s2 * 0.0078125f - mu * mu + 1e-5f);
        float4 o;
        o.x = (h.x - mu) * rs * gv3.x + bv3.x; o.y = (h.y - mu) * rs * gv3.y + bv3.y;
        o.z = (h.z - mu) * rs * gv3.z + bv3.z; o.w = (h.w - mu) * rs * gv3.w + bv3.w;
        o.x = fmaxf(o.x, 0.01f * o.x); o.y = fmaxf(o.y, 0.01f * o.y);
        o.z = fmaxf(o.z, 0.01f * o.z); o.w = fmaxf(o.w, 0.01f * o.w);
        *(float4*)(out + (size_t)n * 128 + l * 4) = o;
    }
}

extern "C" void kernel_launch(void* const* d_in, const int* in_sizes, int n_in,
                              void* d_out, int out_size) {
    const float* x       = (const float*)d_in[0];
    const int*   nidx    = (const int*)d_in[1];
    const float* W_self  = (const float*)d_in[2];
    const float* b_self  = (const float*)d_in[3];
    const float* W_neigh = (const float*)d_in[4];
    const float* b_neigh = (const float*)d_in[5];
    const float* W_ih    = (const float*)d_in[6];
    const float* W_hh    = (const float*)d_in[7];
    const float* b_ih    = (const float*)d_in[8];
    const float* b_hh    = (const float*)d_in[9];
    const float* g1      = (const float*)d_in[10];
    const float* bt1     = (const float*)d_in[11];
    const float* g3      = (const float*)d_in[12];
    const float* bt3     = (const float*)d_in[13];
    float* out = (float*)d_out;

    cudaFuncSetAttribute(y_kernel, cudaFuncAttributeMaxDynamicSharedMemorySize, 148480);
    cudaFuncSetAttribute(lstm_kernel, cudaFuncAttributeMaxDynamicSharedMemorySize, 184832);

    int blocks = (NN + TN - 1) / TN;
    prep_kernel<<<256, 256>>>(W_ih, W_hh, W_self, W_neigh);
    y_kernel<<<blocks, 256, 148480>>>(x, b_ih);
    lstm_kernel<<<blocks, 256, 184832>>>(x, nidx, b_hh, b_self, b_neigh, g1, bt1, g3, bt3, out);
}

// round 7
// speedup vs baseline: 2.0531x; 2.0531x over previous
#include <cuda_runtime.h>
#include <cuda_bf16.h>

#define NN 50000
#define TN 32
typedef unsigned long long u64;
typedef unsigned int u32;

__device__ __align__(256) float g_y[(size_t)NN * 512];      // gate-interleaved: [node][unit*4+type]
__device__ __align__(256) float g_h[(size_t)NN * 128];
__device__ __align__(256) float g_WihT[128 * 512];
__device__ __align__(256) float g_WselfT[128 * 128];
__device__ __align__(256) float g_WneighT[128 * 128];
__device__ __align__(256) __nv_bfloat16 g_Wp[512 * 136];    // permuted W_hh, 272B row stride

// ---- fp32x2 helpers ----
__device__ __forceinline__ u64 pack2(float lo, float hi) {
    u64 r; asm("mov.b64 %0,{%1,%2};" : "=l"(r) : "f"(lo), "f"(hi)); return r;
}
__device__ __forceinline__ u64 pack2s(float v) { return pack2(v, v); }
__device__ __forceinline__ void unpack2(u64 v, float& lo, float& hi) {
    asm("mov.b64 {%0,%1},%2;" : "=f"(lo), "=f"(hi) : "l"(v));
}
__device__ __forceinline__ void ffma2(u64& d, u64 a, u64 b) {
    asm("fma.rn.f32x2 %0,%1,%2,%0;" : "+l"(d) : "l"(a), "l"(b));
}
__device__ __forceinline__ void cp16(void* dst, const void* src) {
    unsigned sa = (unsigned)__cvta_generic_to_shared(dst);
    asm volatile("cp.async.cg.shared.global [%0],[%1],16;" :: "r"(sa), "l"(src) : "memory");
}
__device__ __forceinline__ void cp_commit() { asm volatile("cp.async.commit_group;" ::: "memory"); }
template <int W> __device__ __forceinline__ void cp_wait() {
    asm volatile("cp.async.wait_group %0;" :: "n"(W) : "memory");
}
__device__ __forceinline__ void cp_chunk(float* dstS, const float* src, int tid) {
#pragma unroll
    for (int i = 0; i < 16; ++i) { int f4 = i * 256 + tid; cp16(dstS + f4 * 4, src + f4 * 4); }
}
__device__ __forceinline__ float sigf(float v) { return __fdividef(1.f, 1.f + __expf(-v)); }
__device__ __forceinline__ float tanhf_fast(float v) { return 1.f - __fdividef(2.f, __expf(2.f * v) + 1.f); }

// ---- tensor-core (legacy mma.sync path, baseline sm_100) ----
__device__ __forceinline__ u32 smem_u32(const void* p) {
    u32 a; asm("{ .reg .u64 t; cvta.to.shared.u64 t,%1; cvt.u32.u64 %0,t; }" : "=r"(a) : "l"(p)); return a;
}
__device__ __forceinline__ void ldmA(u32* r, u32 a) {
    asm volatile("ldmatrix.sync.aligned.m8n8.x4.shared.b16 {%0,%1,%2,%3},[%4];"
        : "=r"(r[0]), "=r"(r[1]), "=r"(r[2]), "=r"(r[3]) : "r"(a));
}
__device__ __forceinline__ void ldmB(u32* r, u32 a) {
    asm volatile("ldmatrix.sync.aligned.m8n8.x2.shared.b16 {%0,%1},[%2];"
        : "=r"(r[0]), "=r"(r[1]) : "r"(a));
}
__device__ __forceinline__ void mmabf(float* d, const u32* a, const u32* b) {
    asm volatile("mma.sync.aligned.m16n8k16.row.col.f32.bf16.bf16.f32 "
        "{%0,%1,%2,%3},{%4,%5,%6,%7},{%8,%9},{%0,%1,%2,%3};"
        : "+f"(d[0]), "+f"(d[1]), "+f"(d[2]), "+f"(d[3])
        : "r"(a[0]), "r"(a[1]), "r"(a[2]), "r"(a[3]), "r"(b[0]), "r"(b[1]));
}

// lstm smem (bytes): W[139264] | A: 2 bufs x (hi[17408] + lo[17408]) | sidx[4096]
// 64 nodes/CTA, A row stride 272 B (128 units x bf16 = 256 B + 16 pad)
#define W_OFF 0
#define A_OFF 139264
#define ATERM 17408
#define ABUF  34816
#define SIDX_OFF 208896
#define LSTM_SMEM 212992
#define NODES 64

// ---- prep ----
__global__ void prep_kernel(const float* __restrict__ W_ih, const float* __restrict__ W_hh,
                            const float* __restrict__ W_self, const float* __restrict__ W_neigh) {
    int i = blockIdx.x * 256 + threadIdx.x;
    if (i < 512 * 128) {
        int g = i >> 7, k = i & 127;
        g_WihT[k * 512 + g] = W_ih[i];
        int type = g >> 7, u = g & 127;
        g_Wp[(((u << 2) | type) * 136) + k] = __float2bfloat16(W_hh[i]);
    }
    if (i < 128 * 128) {
        int jj = i & 127, k = i >> 7;
        g_WselfT[k * 128 + jj] = W_self[jj * 128 + k];
        g_WneighT[k * 128 + jj] = W_neigh[jj * 128 + k];
    }
}

#define HSTR 34
__device__ __forceinline__ void stage_tile(float* sm, const float* __restrict__ src, int base, int tid) {
    int node = tid >> 3, q = tid & 7, n = base + node;
#pragma unroll
    for (int u = 0; u < 4; ++u) {
        float4 v = make_float4(0.f, 0.f, 0.f, 0.f);
        if (n < NN) v = ((const float4*)(src + (size_t)n * 128))[q * 4 + u];
        int k0 = q * 16 + u * 4;
        sm[(k0 + 0) * HSTR + node] = v.x; sm[(k0 + 1) * HSTR + node] = v.y;
        sm[(k0 + 2) * HSTR + node] = v.z; sm[(k0 + 3) * HSTR + node] = v.w;
    }
}

// ---- y = x @ W_ih^T + b_ih + b_hh, stored gate-interleaved ----
__global__ __launch_bounds__(256, 1) void y_kernel(const float* __restrict__ x,
                                                   const float* __restrict__ b_ih,
                                                   const float* __restrict__ b_hh) {
    extern __shared__ float smem[];
    float* buf[2] = { smem, smem + 16384 };
    float* sm_x = smem + 32768;
    const int tid = threadIdx.x, j = tid & 127, ng = tid >> 7, base = blockIdx.x * TN;

    cp_chunk(buf[0], g_WihT, tid); cp_commit();
    stage_tile(sm_x, x, base, tid);

    float bi = b_ih[j] + b_hh[j], bf = b_ih[128 + j] + b_hh[128 + j];
    float bg = b_ih[256 + j] + b_hh[256 + j], bo = b_ih[384 + j] + b_hh[384 + j];
    u64 ai[8], af[8], ag[8], ao[8];
#pragma unroll
    for (int p = 0; p < 8; ++p) { ai[p] = pack2s(bi); af[p] = pack2s(bf); ag[p] = pack2s(bg); ao[p] = pack2s(bo); }

    int cur = 0;
#pragma unroll 1
    for (int kc = 0; kc < 4; ++kc) {
        __syncthreads();
        if (kc < 3) { cp_chunk(buf[cur ^ 1], g_WihT + (kc + 1) * 16384, tid); cp_commit(); cp_wait<1>(); }
        else cp_wait<0>();
        __syncthreads();
        const float* Wb = buf[cur];
        const float* act = sm_x + kc * 32 * HSTR + ng * 16;
#pragma unroll 8
        for (int kk = 0; kk < 32; ++kk) {
            const float* wr = Wb + kk * 512 + j;
            u64 wi = pack2s(wr[0]), wf = pack2s(wr[128]), wg = pack2s(wr[256]), wo = pack2s(wr[384]);
            const u64* hp = (const u64*)(act + kk * HSTR);
#pragma unroll
            for (int p = 0; p < 8; ++p) {
                u64 hv = hp[p];
                ffma2(ai[p], wi, hv); ffma2(af[p], wf, hv);
                ffma2(ag[p], wg, hv); ffma2(ao[p], wo, hv);
            }
        }
        cur ^= 1;
    }
#pragma unroll
    for (int p = 0; p < 8; ++p) {
        int n0 = base + ng * 16 + 2 * p, n1 = n0 + 1;
        float i0, i1, f0, f1, q0, q1, o0, o1;
        unpack2(ai[p], i0, i1); unpack2(af[p], f0, f1);
        unpack2(ag[p], q0, q1); unpack2(ao[p], o0, o1);
        if (n0 < NN) *(float4*)(g_y + (size_t)n0 * 512 + 4 * j) = make_float4(i0, f0, q0, o0);
        if (n1 < NN) *(float4*)(g_y + (size_t)n1 * 512 + 4 * j) = make_float4(i1, f1, q1, o1);
    }
}

// ---- LSTM: 64 nodes/CTA, mma.sync bf16 hi/lo recurrence ----
__global__ __launch_bounds__(256, 1) void lstm64(const int* __restrict__ nidx) {
    extern __shared__ char sb[];
    u32 sbase = smem_u32(sb);
    const int tid = threadIdx.x, w = tid >> 5, lane = tid & 31;
    const int base = blockIdx.x * NODES;
    int* sidx = (int*)(sb + SIDX_OFF);

    // load permuted W_hh (139264 B = 8704 x 16B)
#pragma unroll
    for (int i = 0; i < 34; ++i) { int c16 = i * 256 + tid; cp16(sb + c16 * 16, (const char*)g_Wp + c16 * 16); }
    cp_commit();
    for (int i = tid; i < NODES * 16; i += 256) {
        int n = base + (i >> 4);
        sidx[i] = (n < NN) ? nidx[n * 16 + (i & 15)] : 0;
    }

    const int g = lane >> 2, codd = lane & 1, chi = (lane >> 1) & 1;
    const int rowl = g + codd * 8;              // node row within m-tile handled by this lane
    const int kgb = w * 16 + chi;               // unit base for this lane's cells

    float cst[32];
#pragma unroll
    for (int i = 0; i < 32; ++i) cst[i] = 0.f;

    cp_wait<0>();
    __syncthreads();

    // ---- t = 0: gates = y only, write h into A buffer 0 ----
#pragma unroll 1
    for (int mt = 0; mt < 4; ++mt) {
        int rn = sidx[(mt * 16 + rowl) * 16];
        const float* yb = g_y + (size_t)rn * 512 + w * 64 + chi * 4;
        u32 hoff = sbase + A_OFF + (u32)(mt * 16 + rowl) * 272;
#pragma unroll
        for (int j = 0; j < 8; ++j) {
            float4 yv = *(const float4*)(yb + j * 8);
            float cc = sigf(yv.x) * tanhf_fast(yv.z);
            cst[mt * 8 + j] = cc;
            float h = sigf(yv.w) * tanhf_fast(cc);
            __nv_bfloat16 bh = __float2bfloat16(h);
            __nv_bfloat16 bl = __float2bfloat16(h - __bfloat162float(bh));
            u32 a = hoff + (u32)(kgb + 2 * j) * 2;
            asm volatile("st.shared.b16 [%0],%1;" :: "r"(a), "h"(*(unsigned short*)&bh) : "memory");
            asm volatile("st.shared.b16 [%0],%1;" :: "r"(a + ATERM), "h"(*(unsigned short*)&bl) : "memory");
        }
    }

    // ---- t = 1..15 ----
#pragma unroll 1
    for (int t = 1; t < 16; ++t) {
        __syncthreads();
        const u32 rdA = sbase + A_OFF + (u32)(((t - 1) & 1) * ABUF);
        const u32 wrA = sbase + A_OFF + (u32)((t & 1) * ABUF);
        const u32 aLaneA = rdA + (u32)(lane & 15) * 272 + (u32)(lane & 16);
        const u32 aLaneB = sbase + W_OFF + (u32)(w * 64 + (lane & 7)) * 272 + (u32)((lane & 8) * 2);
#pragma unroll 1
        for (int mt = 0; mt < 4; ++mt) {
            int rn = sidx[(mt * 16 + rowl) * 16 + t];
            const float* yb = g_y + (size_t)rn * 512 + w * 64 + chi * 4;
            float4 yv[8];
#pragma unroll
            for (int j = 0; j < 8; ++j) yv[j] = *(const float4*)(yb + j * 8);

            float D[8][4];
#pragma unroll
            for (int j = 0; j < 8; ++j) { D[j][0] = 0.f; D[j][1] = 0.f; D[j][2] = 0.f; D[j][3] = 0.f; }

            u32 amt = aLaneA + (u32)(mt * 16) * 272;
#pragma unroll
            for (int kk = 0; kk < 8; ++kk) {
                u32 ahi[4], alo[4];
                u32 ak = amt + kk * 32;
                ldmA(ahi, ak);
                ldmA(alo, ak + ATERM);
#pragma unroll
                for (int nt = 0; nt < 8; ++nt) {
                    u32 b[2];
                    ldmB(b, aLaneB + (u32)(nt * 8) * 272 + kk * 32);
                    mmabf(D[nt], ahi, b);
                    mmabf(D[nt], alo, b);
                }
            }

            u32 hoff = wrA + (u32)(mt * 16 + rowl) * 272;
            int gn = base + mt * 16 + rowl;
#pragma unroll
            for (int nt = 0; nt < 8; ++nt) {
                float s0 = __shfl_xor_sync(~0u, D[nt][0], 1);
                float s1 = __shfl_xor_sync(~0u, D[nt][1], 1);
                float s2 = __shfl_xor_sync(~0u, D[nt][2], 1);
                float s3 = __shfl_xor_sync(~0u, D[nt][3], 1);
                float vi, vf, vg, vo;
                if (codd == 0) { vi = D[nt][0]; vf = D[nt][1]; vg = s0; vo = s1; }
                else           { vi = s2;       vf = s3;       vg = D[nt][2]; vo = D[nt][3]; }
                float4 y4 = yv[nt];
                vi += y4.x; vf += y4.y; vg += y4.z; vo += y4.w;
                int ci = mt * 8 + nt;
                float cc = sigf(vf) * cst[ci] + sigf(vi) * tanhf_fast(vg);
                cst[ci] = cc;
                float h = sigf(vo) * tanhf_fast(cc);
                __nv_bfloat16 bh = __float2bfloat16(h);
                __nv_bfloat16 bl = __float2bfloat16(h - __bfloat162float(bh));
                u32 a = hoff + (u32)(kgb + 2 * nt) * 2;
                asm volatile("st.shared.b16 [%0],%1;" :: "r"(a), "h"(*(unsigned short*)&bh) : "memory");
                asm volatile("st.shared.b16 [%0],%1;" :: "r"(a + ATERM), "h"(*(unsigned short*)&bl) : "memory");
                if (t == 15 && gn < NN) g_h[(size_t)gn * 128 + kgb + 2 * nt] = h;
            }
        }
    }
}

// ---- epilogue ----
__global__ __launch_bounds__(256, 1) void epi_kernel(
    const float* __restrict__ x, const float* __restrict__ b_self, const float* __restrict__ b_neigh,
    const float* __restrict__ g1, const float* __restrict__ bt1,
    const float* __restrict__ g3, const float* __restrict__ bt3, float* __restrict__ out) {
    extern __shared__ float smem[];
    float* ws = smem;
    float* wn = smem + 16384;
    float* sm_x = smem + 32768;
    float* sm_h = smem + 37120;
    float* sm_r = smem + 41472;
    const int tid = threadIdx.x, j = tid & 127, ng = tid >> 7, base = blockIdx.x * TN;

    cp_chunk(ws, g_WselfT, tid); cp_chunk(wn, g_WneighT, tid); cp_commit();
    stage_tile(sm_x, x, base, tid);
    stage_tile(sm_h, g_h, base, tid);
    cp_wait<0>();
    __syncthreads();

    float bsn = b_self[j] + b_neigh[j];
    u64 racc[8];
#pragma unroll
    for (int p = 0; p < 8; ++p) racc[p] = pack2s(bsn);
#pragma unroll 4
    for (int k = 0; k < 128; ++k) {
        u64 wsv = pack2s(ws[k * 128 + j]);
        u64 wnv = pack2s(wn[k * 128 + j]);
        const u64* xp = (const u64*)(sm_x + k * HSTR + ng * 16);
        const u64* hp = (const u64*)(sm_h + k * HSTR + ng * 16);
#pragma unroll
        for (int p = 0; p < 8; ++p) { ffma2(racc[p], wsv, xp[p]); ffma2(racc[p], wnv, hp[p]); }
    }
#pragma unroll
    for (int p = 0; p < 8; ++p) {
        float lo, hi; unpack2(racc[p], lo, hi);
        int node = ng * 16 + 2 * p;
        sm_r[node * 132 + j] = lo;
        sm_r[(node + 1) * 132 + j] = hi;
    }
    __syncthreads();

    int w = tid >> 5, l = tid & 31;
    float4 gv1 = *(const float4*)(g1 + l * 4), bv1 = *(const float4*)(bt1 + l * 4);
    float4 gv3 = *(const float4*)(g3 + l * 4), bv3 = *(const float4*)(bt3 + l * 4);
#pragma unroll 1
    for (int q = 0; q < 4; ++q) {
        int node = w * 4 + q, n = base + node;
        if (n >= NN) break;
        float4 rv = *(float4*)(sm_r + node * 132 + l * 4);
        float4 xv = *(const float4*)(x + (size_t)n * 128 + l * 4);
        float s1 = rv.x + rv.y + rv.z + rv.w;
        float s2 = rv.x * rv.x + rv.y * rv.y + rv.z * rv.z + rv.w * rv.w;
#pragma unroll
        for (int mm = 16; mm > 0; mm >>= 1) { s1 += __shfl_xor_sync(~0u, s1, mm); s2 += __shfl_xor_sync(~0u, s2, mm); }
        float mu = s1 * 0.0078125f;
        float rs = rsqrtf(s2 * 0.0078125f - mu * mu + 1e-5f);
        float4 h;
        h.x = (rv.x - mu) * rs * gv1.x + bv1.x; h.y = (rv.y - mu) * rs * gv1.y + bv1.y;
        h.z = (rv.z - mu) * rs * gv1.z + bv1.z; h.w = (rv.w - mu) * rs * gv1.w + bv1.w;
        h.x = fmaxf(h.x, 0.01f * h.x) + xv.x; h.y = fmaxf(h.y, 0.01f * h.y) + xv.y;
        h.z = fmaxf(h.z, 0.01f * h.z) + xv.z; h.w = fmaxf(h.w, 0.01f * h.w) + xv.w;
        s1 = h.x + h.y + h.z + h.w;
        s2 = h.x * h.x + h.y * h.y + h.z * h.z + h.w * h.w;
#pragma unroll
        for (int mm = 16; mm > 0; mm >>= 1) { s1 += __shfl_xor_sync(~0u, s1, mm); s2 += __shfl_xor_sync(~0u, s2, mm); }
        mu = s1 * 0.0078125f;
        rs = rsqrtf(s2 * 0.0078125f - mu * mu + 1e-5f);
        float4 o;
        o.x = (h.x - mu) * rs * gv3.x + bv3.x; o.y = (h.y - mu) * rs * gv3.y + bv3.y;
        o.z = (h.z - mu) * rs * gv3.z + bv3.z; o.w = (h.w - mu) * rs * gv3.w + bv3.w;
        o.x = fmaxf(o.x, 0.01f * o.x); o.y = fmaxf(o.y, 0.01f * o.y);
        o.z = fmaxf(o.z, 0.01f * o.z); o.w = fmaxf(o.w, 0.01f * o.w);
        *(float4*)(out + (size_t)n * 128 + l * 4) = o;
    }
}

extern "C" void kernel_launch(void* const* d_in, const int* in_sizes, int n_in,
                              void* d_out, int out_size) {
    const float* x       = (const float*)d_in[0];
    const int*   nidx    = (const int*)d_in[1];
    const float* W_self  = (const float*)d_in[2];
    const float* b_self  = (const float*)d_in[3];
    const float* W_neigh = (const float*)d_in[4];
    const float* b_neigh = (const float*)d_in[5];
    const float* W_ih    = (const float*)d_in[6];
    const float* W_hh    = (const float*)d_in[7];
    const float* b_ih    = (const float*)d_in[8];
    const float* b_hh    = (const float*)d_in[9];
    const float* g1      = (const float*)d_in[10];
    const float* bt1     = (const float*)d_in[11];
    const float* g3      = (const float*)d_in[12];
    const float* bt3     = (const float*)d_in[13];
    float* out = (float*)d_out;

    cudaFuncSetAttribute(y_kernel,   cudaFuncAttributeMaxDynamicSharedMemorySize, 148480);
    cudaFuncSetAttribute(lstm64,     cudaFuncAttributeMaxDynamicSharedMemorySize, LSTM_SMEM);
    cudaFuncSetAttribute(epi_kernel, cudaFuncAttributeMaxDynamicSharedMemorySize, 182784);

    int blk32 = (NN + TN - 1) / TN;        // 1563
    int blk64 = (NN + NODES - 1) / NODES;  // 782
    prep_kernel<<<256, 256>>>(W_ih, W_hh, W_self, W_neigh);
    y_kernel<<<blk32, 256, 148480>>>(x, b_ih, b_hh);
    lstm64<<<blk64, 256, LSTM_SMEM>>>(nidx);
    epi_kernel<<<blk32, 256, 182784>>>(x, b_self, b_neigh, g1, bt1, g3, bt3, out);
}

// round 8
// speedup vs baseline: 2.1005x; 1.0231x over previous
#include <cuda_runtime.h>
#include <cuda_bf16.h>
#include <cuda_fp16.h>

#define NN 50000
#define TN 32
typedef unsigned long long u64;
typedef unsigned int u32;

__device__ __align__(256) __half g_yh[(size_t)NN * 512];    // gate-interleaved fp16: [node][unit*4+type]
__device__ __align__(256) float g_h[(size_t)NN * 128];
__device__ __align__(256) float g_WihT[128 * 512];
__device__ __align__(256) float g_WselfT[128 * 128];
__device__ __align__(256) float g_WneighT[128 * 128];
__device__ __align__(256) __nv_bfloat16 g_Wp[512 * 136];    // permuted W_hh, 272B row stride

// ---- fp32x2 helpers ----
__device__ __forceinline__ u64 pack2(float lo, float hi) {
    u64 r; asm("mov.b64 %0,{%1,%2};" : "=l"(r) : "f"(lo), "f"(hi)); return r;
}
__device__ __forceinline__ u64 pack2s(float v) { return pack2(v, v); }
__device__ __forceinline__ void unpack2(u64 v, float& lo, float& hi) {
    asm("mov.b64 {%0,%1},%2;" : "=f"(lo), "=f"(hi) : "l"(v));
}
__device__ __forceinline__ void ffma2(u64& d, u64 a, u64 b) {
    asm("fma.rn.f32x2 %0,%1,%2,%0;" : "+l"(d) : "l"(a), "l"(b));
}
__device__ __forceinline__ void cp16(void* dst, const void* src) {
    unsigned sa = (unsigned)__cvta_generic_to_shared(dst);
    asm volatile("cp.async.cg.shared.global [%0],[%1],16;" :: "r"(sa), "l"(src) : "memory");
}
__device__ __forceinline__ void cp_commit() { asm volatile("cp.async.commit_group;" ::: "memory"); }
template <int W> __device__ __forceinline__ void cp_wait() {
    asm volatile("cp.async.wait_group %0;" :: "n"(W) : "memory");
}
__device__ __forceinline__ void cp_chunk(float* dstS, const float* src, int tid) {
#pragma unroll
    for (int i = 0; i < 16; ++i) { int f4 = i * 256 + tid; cp16(dstS + f4 * 4, src + f4 * 4); }
}
// ---- fast activations: tanh.approx (baseline PTX, sm_75+) ----
__device__ __forceinline__ float tanha(float x) {
    float r; asm("tanh.approx.f32 %0,%1;" : "=f"(r) : "f"(x)); return r;
}
__device__ __forceinline__ float sigt(float x) { return fmaf(tanha(0.5f * x), 0.5f, 0.5f); }

// ---- tensor-core (legacy mma.sync path, baseline sm_100) ----
__device__ __forceinline__ u32 smem_u32(const void* p) {
    u32 a; asm("{ .reg .u64 t; cvta.to.shared.u64 t,%1; cvt.u32.u64 %0,t; }" : "=r"(a) : "l"(p)); return a;
}
__device__ __forceinline__ void ldmA(u32* r, u32 a) {
    asm volatile("ldmatrix.sync.aligned.m8n8.x4.shared.b16 {%0,%1,%2,%3},[%4];"
        : "=r"(r[0]), "=r"(r[1]), "=r"(r[2]), "=r"(r[3]) : "r"(a));
}
__device__ __forceinline__ void ldmB(u32* r, u32 a) {
    asm volatile("ldmatrix.sync.aligned.m8n8.x2.shared.b16 {%0,%1},[%2];"
        : "=r"(r[0]), "=r"(r[1]) : "r"(a));
}
__device__ __forceinline__ void mmabf(float* d, const u32* a, const u32* b) {
    asm volatile("mma.sync.aligned.m16n8k16.row.col.f32.bf16.bf16.f32 "
        "{%0,%1,%2,%3},{%4,%5,%6,%7},{%8,%9},{%0,%1,%2,%3};"
        : "+f"(d[0]), "+f"(d[1]), "+f"(d[2]), "+f"(d[3])
        : "r"(a[0]), "r"(a[1]), "r"(a[2]), "r"(a[3]), "r"(b[0]), "r"(b[1]));
}

// lstm smem (bytes): W[139264] | A: 2 bufs x (hi[17408] + lo[17408]) | sidx[4096]
#define W_OFF 0
#define A_OFF 139264
#define ATERM 17408
#define ABUF  34816
#define SIDX_OFF 208896
#define LSTM_SMEM 212992
#define NODES 64

// ---- prep ----
__global__ void prep_kernel(const float* __restrict__ W_ih, const float* __restrict__ W_hh,
                            const float* __restrict__ W_self, const float* __restrict__ W_neigh) {
    int i = blockIdx.x * 256 + threadIdx.x;
    if (i < 512 * 128) {
        int g = i >> 7, k = i & 127;
        g_WihT[k * 512 + g] = W_ih[i];
        int type = g >> 7, u = g & 127;
        g_Wp[(((u << 2) | type) * 136) + k] = __float2bfloat16(W_hh[i]);
    }
    if (i < 128 * 128) {
        int jj = i & 127, k = i >> 7;
        g_WselfT[k * 128 + jj] = W_self[jj * 128 + k];
        g_WneighT[k * 128 + jj] = W_neigh[jj * 128 + k];
    }
}

#define HSTR 34
__device__ __forceinline__ void stage_tile(float* sm, const float* __restrict__ src, int base, int tid) {
    int node = tid >> 3, q = tid & 7, n = base + node;
#pragma unroll
    for (int u = 0; u < 4; ++u) {
        float4 v = make_float4(0.f, 0.f, 0.f, 0.f);
        if (n < NN) v = ((const float4*)(src + (size_t)n * 128))[q * 4 + u];
        int k0 = q * 16 + u * 4;
        sm[(k0 + 0) * HSTR + node] = v.x; sm[(k0 + 1) * HSTR + node] = v.y;
        sm[(k0 + 2) * HSTR + node] = v.z; sm[(k0 + 3) * HSTR + node] = v.w;
    }
}

// ---- y = x @ W_ih^T + b_ih + b_hh, stored gate-interleaved fp16 ----
__global__ __launch_bounds__(256, 1) void y_kernel(const float* __restrict__ x,
                                                   const float* __restrict__ b_ih,
                                                   const float* __restrict__ b_hh) {
    extern __shared__ float smem[];
    float* buf[2] = { smem, smem + 16384 };
    float* sm_x = smem + 32768;
    const int tid = threadIdx.x, j = tid & 127, ng = tid >> 7, base = blockIdx.x * TN;

    cp_chunk(buf[0], g_WihT, tid); cp_commit();
    stage_tile(sm_x, x, base, tid);

    float bi = b_ih[j] + b_hh[j], bf = b_ih[128 + j] + b_hh[128 + j];
    float bg = b_ih[256 + j] + b_hh[256 + j], bo = b_ih[384 + j] + b_hh[384 + j];
    u64 ai[8], af[8], ag[8], ao[8];
#pragma unroll
    for (int p = 0; p < 8; ++p) { ai[p] = pack2s(bi); af[p] = pack2s(bf); ag[p] = pack2s(bg); ao[p] = pack2s(bo); }

    int cur = 0;
#pragma unroll 1
    for (int kc = 0; kc < 4; ++kc) {
        __syncthreads();
        if (kc < 3) { cp_chunk(buf[cur ^ 1], g_WihT + (kc + 1) * 16384, tid); cp_commit(); cp_wait<1>(); }
        else cp_wait<0>();
        __syncthreads();
        const float* Wb = buf[cur];
        const float* act = sm_x + kc * 32 * HSTR + ng * 16;
#pragma unroll 8
        for (int kk = 0; kk < 32; ++kk) {
            const float* wr = Wb + kk * 512 + j;
            u64 wi = pack2s(wr[0]), wf = pack2s(wr[128]), wg = pack2s(wr[256]), wo = pack2s(wr[384]);
            const u64* hp = (const u64*)(act + kk * HSTR);
#pragma unroll
            for (int p = 0; p < 8; ++p) {
                u64 hv = hp[p];
                ffma2(ai[p], wi, hv); ffma2(af[p], wf, hv);
                ffma2(ag[p], wg, hv); ffma2(ao[p], wo, hv);
            }
        }
        cur ^= 1;
    }
#pragma unroll
    for (int p = 0; p < 8; ++p) {
        int n0 = base + ng * 16 + 2 * p, n1 = n0 + 1;
        float i0, i1, f0, f1, q0, q1, o0, o1;
        unpack2(ai[p], i0, i1); unpack2(af[p], f0, f1);
        unpack2(ag[p], q0, q1); unpack2(ao[p], o0, o1);
        if (n0 < NN) {
            __half2 a = __floats2half2_rn(i0, f0), b = __floats2half2_rn(q0, o0);
            u64 v = (u64)(*(u32*)&a) | ((u64)(*(u32*)&b) << 32);
            *(u64*)(g_yh + (size_t)n0 * 512 + 4 * j) = v;
        }
        if (n1 < NN) {
            __half2 a = __floats2half2_rn(i1, f1), b = __floats2half2_rn(q1, o1);
            u64 v = (u64)(*(u32*)&a) | ((u64)(*(u32*)&b) << 32);
            *(u64*)(g_yh + (size_t)n1 * 512 + 4 * j) = v;
        }
    }
}

// unpack fp16 gate quad
__device__ __forceinline__ void unpack_y(u64 raw, float& vi, float& vf, float& vg, float& vo) {
    u32 w0 = (u32)raw, w1 = (u32)(raw >> 32);
    float2 p = __half22float2(*(__half2*)&w0);
    float2 q = __half22float2(*(__half2*)&w1);
    vi = p.x; vf = p.y; vg = q.x; vo = q.y;
}

// ---- LSTM: 64 nodes/CTA, mma.sync bf16 hi/lo recurrence ----
__global__ __launch_bounds__(256, 1) void lstm64(const int* __restrict__ nidx) {
    extern __shared__ char sb[];
    u32 sbase = smem_u32(sb);
    const int tid = threadIdx.x, w = tid >> 5, lane = tid & 31;
    const int base = blockIdx.x * NODES;
    int* sidx = (int*)(sb + SIDX_OFF);

#pragma unroll
    for (int i = 0; i < 34; ++i) { int c16 = i * 256 + tid; cp16(sb + c16 * 16, (const char*)g_Wp + c16 * 16); }
    cp_commit();
    for (int i = tid; i < NODES * 16; i += 256) {
        int n = base + (i >> 4);
        sidx[i] = (n < NN) ? nidx[n * 16 + (i & 15)] : 0;
    }

    const int g = lane >> 2, codd = lane & 1, chi = (lane >> 1) & 1;
    const int rowl = g + codd * 8;
    const int kgb = w * 16 + chi;
    const u32 ybOff = (u32)(w * 64 + chi * 4);

    float cst[32];
#pragma unroll
    for (int i = 0; i < 32; ++i) cst[i] = 0.f;

    cp_wait<0>();
    __syncthreads();

    // ---- t = 0: gates = y only ----
#pragma unroll 1
    for (int mt = 0; mt < 4; ++mt) {
        int rn = sidx[(mt * 16 + rowl) * 16];
        const __half* yb = g_yh + (size_t)rn * 512 + ybOff;
        u32 hoff = sbase + A_OFF + (u32)(mt * 16 + rowl) * 272;
#pragma unroll
        for (int j = 0; j < 8; ++j) {
            float vi, vf, vg, vo;
            unpack_y(*(const u64*)(yb + j * 8), vi, vf, vg, vo);
            float cc = sigt(vi) * tanha(vg);
            cst[mt * 8 + j] = cc;
            float h = sigt(vo) * tanha(cc);
            __nv_bfloat16 bh = __float2bfloat16(h);
            __nv_bfloat16 bl = __float2bfloat16(h - __bfloat162float(bh));
            u32 a = hoff + (u32)(kgb + 2 * j) * 2;
            asm volatile("st.shared.b16 [%0],%1;" :: "r"(a), "h"(*(unsigned short*)&bh) : "memory");
            asm volatile("st.shared.b16 [%0],%1;" :: "r"(a + ATERM), "h"(*(unsigned short*)&bl) : "memory");
        }
    }

    u64 ybufA[8], ybufB[8];
    // prefetch (t=1, mt=0)
    {
        int rn = sidx[rowl * 16 + 1];
        const __half* yb = g_yh + (size_t)rn * 512 + ybOff;
#pragma unroll
        for (int j = 0; j < 8; ++j) ybufA[j] = *(const u64*)(yb + j * 8);
    }

    // ---- t = 1..15 ----
#pragma unroll 1
    for (int t = 1; t < 16; ++t) {
        __syncthreads();
        const u32 rdA = sbase + A_OFF + (u32)(((t - 1) & 1) * ABUF);
        const u32 wrA = sbase + A_OFF + (u32)((t & 1) * ABUF);
        const u32 aLaneA = rdA + (u32)(lane & 15) * 272 + (u32)(lane & 16);
        const u32 aLaneB = sbase + W_OFF + (u32)(w * 64 + (lane & 7)) * 272 + (u32)((lane & 8) * 2);
#pragma unroll 1
        for (int mt = 0; mt < 4; ++mt) {
            u64* ycur = (mt & 1) ? ybufB : ybufA;
            u64* ynxt = (mt & 1) ? ybufA : ybufB;
            // prefetch next y tile (next mt, or mt0 of next step)
            {
                int pmt = (mt < 3) ? (mt + 1) : 0;
                int pt = (mt < 3) ? t : (t + 1);
                if (pt < 16) {
                    int rn = sidx[(pmt * 16 + rowl) * 16 + pt];
                    const __half* yb = g_yh + (size_t)rn * 512 + ybOff;
#pragma unroll
                    for (int j = 0; j < 8; ++j) ynxt[j] = *(const u64*)(yb + j * 8);
                }
            }

            float D[8][4];
#pragma unroll
            for (int j = 0; j < 8; ++j) { D[j][0] = 0.f; D[j][1] = 0.f; D[j][2] = 0.f; D[j][3] = 0.f; }

            u32 amt = aLaneA + (u32)(mt * 16) * 272;
#pragma unroll
            for (int kk = 0; kk < 8; ++kk) {
                u32 ahi[4], alo[4];
                u32 ak = amt + kk * 32;
                ldmA(ahi, ak);
                ldmA(alo, ak + ATERM);
#pragma unroll
                for (int nt = 0; nt < 8; ++nt) {
                    u32 b[2];
                    ldmB(b, aLaneB + (u32)(nt * 8) * 272 + kk * 32);
                    mmabf(D[nt], ahi, b);
                    mmabf(D[nt], alo, b);
                }
            }

            u32 hoff = wrA + (u32)(mt * 16 + rowl) * 272;
            int gn = base + mt * 16 + rowl;
#pragma unroll
            for (int nt = 0; nt < 8; ++nt) {
                float s0 = __shfl_xor_sync(~0u, D[nt][0], 1);
                float s1 = __shfl_xor_sync(~0u, D[nt][1], 1);
                float s2 = __shfl_xor_sync(~0u, D[nt][2], 1);
                float s3 = __shfl_xor_sync(~0u, D[nt][3], 1);
                float vi, vf, vg, vo;
                if (codd == 0) { vi = D[nt][0]; vf = D[nt][1]; vg = s0; vo = s1; }
                else           { vi = s2;       vf = s3;       vg = D[nt][2]; vo = D[nt][3]; }
                float yi, yf, yg, yo;
                unpack_y(ycur[nt], yi, yf, yg, yo);
                vi += yi; vf += yf; vg += yg; vo += yo;
                int ci = mt * 8 + nt;
                float cc = sigt(vf) * cst[ci] + sigt(vi) * tanha(vg);
                cst[ci] = cc;
                float h = sigt(vo) * tanha(cc);
                __nv_bfloat16 bh = __float2bfloat16(h);
                __nv_bfloat16 bl = __float2bfloat16(h - __bfloat162float(bh));
                u32 a = hoff + (u32)(kgb + 2 * nt) * 2;
                asm volatile("st.shared.b16 [%0],%1;" :: "r"(a), "h"(*(unsigned short*)&bh) : "memory");
                asm volatile("st.shared.b16 [%0],%1;" :: "r"(a + ATERM), "h"(*(unsigned short*)&bl) : "memory");
                if (t == 15 && gn < NN) g_h[(size_t)gn * 128 + kgb + 2 * nt] = h;
            }
        }
    }
}

// ---- epilogue ----
__global__ __launch_bounds__(256, 1) void epi_kernel(
    const float* __restrict__ x, const float* __restrict__ b_self, const float* __restrict__ b_neigh,
    const float* __restrict__ g1, const float* __restrict__ bt1,
    const float* __restrict__ g3, const float* __restrict__ bt3, float* __restrict__ out) {
    extern __shared__ float smem[];
    float* ws = smem;
    float* wn = smem + 16384;
    float* sm_x = smem + 32768;
    float* sm_h = smem + 37120;
    float* sm_r = smem + 41472;
    const int tid = threadIdx.x, j = tid & 127, ng = tid >> 7, base = blockIdx.x * TN;

    cp_chunk(ws, g_WselfT, tid); cp_chunk(wn, g_WneighT, tid); cp_commit();
    stage_tile(sm_x, x, base, tid);
    stage_tile(sm_h, g_h, base, tid);
    cp_wait<0>();
    __syncthreads();

    float bsn = b_self[j] + b_neigh[j];
    u64 racc[8];
#pragma unroll
    for (int p = 0; p < 8; ++p) racc[p] = pack2s(bsn);
#pragma unroll 4
    for (int k = 0; k < 128; ++k) {
        u64 wsv = pack2s(ws[k * 128 + j]);
        u64 wnv = pack2s(wn[k * 128 + j]);
        const u64* xp = (const u64*)(sm_x + k * HSTR + ng * 16);
        const u64* hp = (const u64*)(sm_h + k * HSTR + ng * 16);
#pragma unroll
        for (int p = 0; p < 8; ++p) { ffma2(racc[p], wsv, xp[p]); ffma2(racc[p], wnv, hp[p]); }
    }
#pragma unroll
    for (int p = 0; p < 8; ++p) {
        float lo, hi; unpack2(racc[p], lo, hi);
        int node = ng * 16 + 2 * p;
        sm_r[node * 132 + j] = lo;
        sm_r[(node + 1) * 132 + j] = hi;
    }
    __syncthreads();

    int w = tid >> 5, l = tid & 31;
    float4 gv1 = *(const float4*)(g1 + l * 4), bv1 = *(const float4*)(bt1 + l * 4);
    float4 gv3 = *(const float4*)(g3 + l * 4), bv3 = *(const float4*)(bt3 + l * 4);
#pragma unroll 1
    for (int q = 0; q < 4; ++q) {
        int node = w * 4 + q, n = base + node;
        if (n >= NN) break;
        float4 rv = *(float4*)(sm_r + node * 132 + l * 4);
        float4 xv = *(const float4*)(x + (size_t)n * 128 + l * 4);
        float s1 = rv.x + rv.y + rv.z + rv.w;
        float s2 = rv.x * rv.x + rv.y * rv.y + rv.z * rv.z + rv.w * rv.w;
#pragma unroll
        for (int mm = 16; mm > 0; mm >>= 1) { s1 += __shfl_xor_sync(~0u, s1, mm); s2 += __shfl_xor_sync(~0u, s2, mm); }
        float mu = s1 * 0.0078125f;
        float rs = rsqrtf(s2 * 0.0078125f - mu * mu + 1e-5f);
        float4 h;
        h.x = (rv.x - mu) * rs * gv1.x + bv1.x; h.y = (rv.y - mu) * rs * gv1.y + bv1.y;
        h.z = (rv.z - mu) * rs * gv1.z + bv1.z; h.w = (rv.w - mu) * rs * gv1.w + bv1.w;
        h.x = fmaxf(h.x, 0.01f * h.x) + xv.x; h.y = fmaxf(h.y, 0.01f * h.y) + xv.y;
        h.z = fmaxf(h.z, 0.01f * h.z) + xv.z; h.w = fmaxf(h.w, 0.01f * h.w) + xv.w;
        s1 = h.x + h.y + h.z + h.w;
        s2 = h.x * h.x + h.y * h.y + h.z * h.z + h.w * h.w;
#pragma unroll
        for (int mm = 16; mm > 0; mm >>= 1) { s1 += __shfl_xor_sync(~0u, s1, mm); s2 += __shfl_xor_sync(~0u, s2, mm); }
        mu = s1 * 0.0078125f;
        rs = rsqrtf(s2 * 0.0078125f - mu * mu + 1e-5f);
        float4 o;
        o.x = (h.x - mu) * rs * gv3.x + bv3.x; o.y = (h.y - mu) * rs * gv3.y + bv3.y;
        o.z = (h.z - mu) * rs * gv3.z + bv3.z; o.w = (h.w - mu) * rs * gv3.w + bv3.w;
        o.x = fmaxf(o.x, 0.01f * o.x); o.y = fmaxf(o.y, 0.01f * o.y);
        o.z = fmaxf(o.z, 0.01f * o.z); o.w = fmaxf(o.w, 0.01f * o.w);
        *(float4*)(out + (size_t)n * 128 + l * 4) = o;
    }
}

extern "C" void kernel_launch(void* const* d_in, const int* in_sizes, int n_in,
                              void* d_out, int out_size) {
    const float* x       = (const float*)d_in[0];
    const int*   nidx    = (const int*)d_in[1];
    const float* W_self  = (const float*)d_in[2];
    const float* b_self  = (const float*)d_in[3];
    const float* W_neigh = (const float*)d_in[4];
    const float* b_neigh = (const float*)d_in[5];
    const float* W_ih    = (const float*)d_in[6];
    const float* W_hh    = (const float*)d_in[7];
    const float* b_ih    = (const float*)d_in[8];
    const float* b_hh    = (const float*)d_in[9];
    const float* g1      = (const float*)d_in[10];
    const float* bt1     = (const float*)d_in[11];
    const float* g3      = (const float*)d_in[12];
    const float* bt3     = (const float*)d_in[13];
    float* out = (float*)d_out;

    cudaFuncSetAttribute(y_kernel,   cudaFuncAttributeMaxDynamicSharedMemorySize, 148480);
    cudaFuncSetAttribute(lstm64,     cudaFuncAttributeMaxDynamicSharedMemorySize, LSTM_SMEM);
    cudaFuncSetAttribute(epi_kernel, cudaFuncAttributeMaxDynamicSharedMemorySize, 182784);

    int blk32 = (NN + TN - 1) / TN;        // 1563
    int blk64 = (NN + NODES - 1) / NODES;  // 782
    prep_kernel<<<256, 256>>>(W_ih, W_hh, W_self, W_neigh);
    y_kernel<<<blk32, 256, 148480>>>(x, b_ih, b_hh);
    lstm64<<<blk64, 256, LSTM_SMEM>>>(nidx);
    epi_kernel<<<blk32, 256, 182784>>>(x, b_self, b_neigh, g1, bt1, g3, bt3, out);
}

// round 9
// speedup vs baseline: 2.7513x; 1.3098x over previous
#include <cuda_runtime.h>
#include <cuda_fp16.h>

#define NN 50000
#define TN 32
typedef unsigned long long u64;
typedef unsigned int u32;

__device__ __align__(256) __half g_yh[(size_t)NN * 512];    // gate-interleaved fp16: [node][unit*4+type]
__device__ __align__(256) float g_h[(size_t)NN * 128];
__device__ __align__(256) float g_WihT[128 * 512];
__device__ __align__(256) float g_WselfT[128 * 128];
__device__ __align__(256) float g_WneighT[128 * 128];
__device__ __align__(256) __half g_Wp[512 * 136];           // permuted fp16 W_hh, 272B row stride

// ---- fp32x2 helpers ----
__device__ __forceinline__ u64 pack2(float lo, float hi) {
    u64 r; asm("mov.b64 %0,{%1,%2};" : "=l"(r) : "f"(lo), "f"(hi)); return r;
}
__device__ __forceinline__ u64 pack2s(float v) { return pack2(v, v); }
__device__ __forceinline__ void unpack2(u64 v, float& lo, float& hi) {
    asm("mov.b64 {%0,%1},%2;" : "=f"(lo), "=f"(hi) : "l"(v));
}
__device__ __forceinline__ void ffma2(u64& d, u64 a, u64 b) {
    asm("fma.rn.f32x2 %0,%1,%2,%0;" : "+l"(d) : "l"(a), "l"(b));
}
__device__ __forceinline__ void cp16(void* dst, const void* src) {
    unsigned sa = (unsigned)__cvta_generic_to_shared(dst);
    asm volatile("cp.async.cg.shared.global [%0],[%1],16;" :: "r"(sa), "l"(src) : "memory");
}
__device__ __forceinline__ void cp_commit() { asm volatile("cp.async.commit_group;" ::: "memory"); }
template <int W> __device__ __forceinline__ void cp_wait() {
    asm volatile("cp.async.wait_group %0;" :: "n"(W) : "memory");
}
__device__ __forceinline__ void cp_chunk(float* dstS, const float* src, int tid) {
#pragma unroll
    for (int i = 0; i < 16; ++i) { int f4 = i * 256 + tid; cp16(dstS + f4 * 4, src + f4 * 4); }
}
// ---- fast activations ----
__device__ __forceinline__ float tanha(float x) {
    float r; asm("tanh.approx.f32 %0,%1;" : "=f"(r) : "f"(x)); return r;
}
__device__ __forceinline__ float sigt(float x) { return fmaf(tanha(0.5f * x), 0.5f, 0.5f); }

// ---- tensor-core (legacy mma.sync, baseline sm_100) ----
__device__ __forceinline__ u32 smem_u32(const void* p) {
    u32 a; asm("{ .reg .u64 t; cvta.to.shared.u64 t,%1; cvt.u32.u64 %0,t; }" : "=r"(a) : "l"(p)); return a;
}
__device__ __forceinline__ void ldmA(u32* r, u32 a) {
    asm volatile("ldmatrix.sync.aligned.m8n8.x4.shared.b16 {%0,%1,%2,%3},[%4];"
        : "=r"(r[0]), "=r"(r[1]), "=r"(r[2]), "=r"(r[3]) : "r"(a));
}
__device__ __forceinline__ void ldmB(u32* r, u32 a) {
    asm volatile("ldmatrix.sync.aligned.m8n8.x2.shared.b16 {%0,%1},[%2];"
        : "=r"(r[0]), "=r"(r[1]) : "r"(a));
}
__device__ __forceinline__ void mmaf16(float* d, const u32* a, const u32* b) {
    asm volatile("mma.sync.aligned.m16n8k16.row.col.f32.f16.f16.f32 "
        "{%0,%1,%2,%3},{%4,%5,%6,%7},{%8,%9},{%0,%1,%2,%3};"
        : "+f"(d[0]), "+f"(d[1]), "+f"(d[2]), "+f"(d[3])
        : "r"(a[0]), "r"(a[1]), "r"(a[2]), "r"(a[3]), "r"(b[0]), "r"(b[1]));
}

// lstm smem (bytes): W[139264] | A: 2 bufs x 17408 (64 rows x 272B fp16) | sidx[4096]
#define W_OFF 0
#define A_OFF 139264
#define ABUF  17408
#define SIDX_OFF 174080
#define LSTM_SMEM 178176
#define NODES 64
#define LTHREADS 512

// ---- prep ----
__global__ void prep_kernel(const float* __restrict__ W_ih, const float* __restrict__ W_hh,
                            const float* __restrict__ W_self, const float* __restrict__ W_neigh) {
    int i = blockIdx.x * 256 + threadIdx.x;
    if (i < 512 * 128) {
        int g = i >> 7, k = i & 127;
        g_WihT[k * 512 + g] = W_ih[i];
        int type = g >> 7, u = g & 127;
        g_Wp[(((u << 2) | type) * 136) + k] = __float2half(W_hh[i]);
    }
    if (i < 128 * 128) {
        int jj = i & 127, k = i >> 7;
        g_WselfT[k * 128 + jj] = W_self[jj * 128 + k];
        g_WneighT[k * 128 + jj] = W_neigh[jj * 128 + k];
    }
}

#define HSTR 34
__device__ __forceinline__ void stage_tile(float* sm, const float* __restrict__ src, int base, int tid) {
    int node = tid >> 3, q = tid & 7, n = base + node;
#pragma unroll
    for (int u = 0; u < 4; ++u) {
        float4 v = make_float4(0.f, 0.f, 0.f, 0.f);
        if (n < NN) v = ((const float4*)(src + (size_t)n * 128))[q * 4 + u];
        int k0 = q * 16 + u * 4;
        sm[(k0 + 0) * HSTR + node] = v.x; sm[(k0 + 1) * HSTR + node] = v.y;
        sm[(k0 + 2) * HSTR + node] = v.z; sm[(k0 + 3) * HSTR + node] = v.w;
    }
}

// ---- y = x @ W_ih^T + b_ih + b_hh, stored gate-interleaved fp16 ----
__global__ __launch_bounds__(256, 1) void y_kernel(const float* __restrict__ x,
                                                   const float* __restrict__ b_ih,
                                                   const float* __restrict__ b_hh) {
    extern __shared__ float smem[];
    float* buf[2] = { smem, smem + 16384 };
    float* sm_x = smem + 32768;
    const int tid = threadIdx.x, j = tid & 127, ng = tid >> 7, base = blockIdx.x * TN;

    cp_chunk(buf[0], g_WihT, tid); cp_commit();
    stage_tile(sm_x, x, base, tid);

    float bi = b_ih[j] + b_hh[j], bf = b_ih[128 + j] + b_hh[128 + j];
    float bg = b_ih[256 + j] + b_hh[256 + j], bo = b_ih[384 + j] + b_hh[384 + j];
    u64 ai[8], af[8], ag[8], ao[8];
#pragma unroll
    for (int p = 0; p < 8; ++p) { ai[p] = pack2s(bi); af[p] = pack2s(bf); ag[p] = pack2s(bg); ao[p] = pack2s(bo); }

    int cur = 0;
#pragma unroll 1
    for (int kc = 0; kc < 4; ++kc) {
        __syncthreads();
        if (kc < 3) { cp_chunk(buf[cur ^ 1], g_WihT + (kc + 1) * 16384, tid); cp_commit(); cp_wait<1>(); }
        else cp_wait<0>();
        __syncthreads();
        const float* Wb = buf[cur];
        const float* act = sm_x + kc * 32 * HSTR + ng * 16;
#pragma unroll 8
        for (int kk = 0; kk < 32; ++kk) {
            const float* wr = Wb + kk * 512 + j;
            u64 wi = pack2s(wr[0]), wf = pack2s(wr[128]), wg = pack2s(wr[256]), wo = pack2s(wr[384]);
            const u64* hp = (const u64*)(act + kk * HSTR);
#pragma unroll
            for (int p = 0; p < 8; ++p) {
                u64 hv = hp[p];
                ffma2(ai[p], wi, hv); ffma2(af[p], wf, hv);
                ffma2(ag[p], wg, hv); ffma2(ao[p], wo, hv);
            }
        }
        cur ^= 1;
    }
#pragma unroll
    for (int p = 0; p < 8; ++p) {
        int n0 = base + ng * 16 + 2 * p, n1 = n0 + 1;
        float i0, i1, f0, f1, q0, q1, o0, o1;
        unpack2(ai[p], i0, i1); unpack2(af[p], f0, f1);
        unpack2(ag[p], q0, q1); unpack2(ao[p], o0, o1);
        if (n0 < NN) {
            __half2 a = __floats2half2_rn(i0, f0), b = __floats2half2_rn(q0, o0);
            u64 v = (u64)(*(u32*)&a) | ((u64)(*(u32*)&b) << 32);
            *(u64*)(g_yh + (size_t)n0 * 512 + 4 * j) = v;
        }
        if (n1 < NN) {
            __half2 a = __floats2half2_rn(i1, f1), b = __floats2half2_rn(q1, o1);
            u64 v = (u64)(*(u32*)&a) | ((u64)(*(u32*)&b) << 32);
            *(u64*)(g_yh + (size_t)n1 * 512 + 4 * j) = v;
        }
    }
}

__device__ __forceinline__ void unpack_y(u64 raw, float& vi, float& vf, float& vg, float& vo) {
    u32 w0 = (u32)raw, w1 = (u32)(raw >> 32);
    float2 p = __half22float2(*(__half2*)&w0);
    float2 q = __half22float2(*(__half2*)&w1);
    vi = p.x; vf = p.y; vg = q.x; vo = q.y;
}

// ---- LSTM: 64 nodes/CTA, 512 threads (16 warps x 8 units), fp16 single-term ----
__global__ __launch_bounds__(LTHREADS, 1) void lstm64(const int* __restrict__ nidx) {
    extern __shared__ char sb[];
    u32 sbase = smem_u32(sb);
    const int tid = threadIdx.x, w = tid >> 5, lane = tid & 31;
    const int base = blockIdx.x * NODES;
    int* sidx = (int*)(sb + SIDX_OFF);

    // load permuted fp16 W_hh (139264 B = 8704 x 16B)
#pragma unroll
    for (int i = 0; i < 17; ++i) { int c16 = i * LTHREADS + tid; cp16(sb + c16 * 16, (const char*)g_Wp + c16 * 16); }
    cp_commit();
    for (int i = tid; i < NODES * 16; i += LTHREADS) {
        int n = base + (i >> 4);
        sidx[i] = (n < NN) ? nidx[n * 16 + (i & 15)] : 0;
    }

    const int g = lane >> 2, codd = lane & 1, chi = (lane >> 1) & 1;
    const int rowl = g + codd * 8;              // node row within m-tile
    const int kgb = w * 8 + chi;                // unit base; cell unit = kgb + 2*nt
    const u32 ybOff = (u32)(w * 32 + chi * 4);

    float cst[16];
#pragma unroll
    for (int i = 0; i < 16; ++i) cst[i] = 0.f;

    cp_wait<0>();
    __syncthreads();

    // ---- t = 0: gates = y only ----
#pragma unroll 1
    for (int mt = 0; mt < 4; ++mt) {
        int rn = sidx[(mt * 16 + rowl) * 16];
        const __half* yb = g_yh + (size_t)rn * 512 + ybOff;
        u32 hoff = sbase + A_OFF + (u32)(mt * 16 + rowl) * 272;
#pragma unroll
        for (int nt = 0; nt < 4; ++nt) {
            float vi, vf, vg, vo;
            unpack_y(*(const u64*)(yb + nt * 8), vi, vf, vg, vo);
            float cc = sigt(vi) * tanha(vg);
            cst[mt * 4 + nt] = cc;
            float h = sigt(vo) * tanha(cc);
            __half bh = __float2half(h);
            asm volatile("st.shared.b16 [%0],%1;" :: "r"(hoff + (u32)(kgb + 2 * nt) * 2),
                         "h"(*(unsigned short*)&bh) : "memory");
        }
    }

    u64 ybufA[4], ybufB[4];
    {
        int rn = sidx[rowl * 16 + 1];
        const __half* yb = g_yh + (size_t)rn * 512 + ybOff;
#pragma unroll
        for (int j = 0; j < 4; ++j) ybufA[j] = *(const u64*)(yb + j * 8);
    }

    // ---- t = 1..15 ----
#pragma unroll 1
    for (int t = 1; t < 16; ++t) {
        __syncthreads();
        const u32 rdA = sbase + A_OFF + (u32)(((t - 1) & 1) * ABUF);
        const u32 wrA = sbase + A_OFF + (u32)((t & 1) * ABUF);
        const u32 aLaneA = rdA + (u32)(lane & 15) * 272 + (u32)(lane & 16);
        const u32 aLaneB = sbase + W_OFF + (u32)(w * 32 + (lane & 7)) * 272 + (u32)((lane & 8) * 2);
#pragma unroll 1
        for (int mt = 0; mt < 4; ++mt) {
            u64* ycur = (mt & 1) ? ybufB : ybufA;
            u64* ynxt = (mt & 1) ? ybufA : ybufB;
            {
                int pmt = (mt < 3) ? (mt + 1) : 0;
                int pt = (mt < 3) ? t : (t + 1);
                if (pt < 16) {
                    int rn = sidx[(pmt * 16 + rowl) * 16 + pt];
                    const __half* yb = g_yh + (size_t)rn * 512 + ybOff;
#pragma unroll
                    for (int j = 0; j < 4; ++j) ynxt[j] = *(const u64*)(yb + j * 8);
                }
            }

            float D[4][4];
#pragma unroll
            for (int j = 0; j < 4; ++j) { D[j][0] = 0.f; D[j][1] = 0.f; D[j][2] = 0.f; D[j][3] = 0.f; }

            u32 amt = aLaneA + (u32)(mt * 16) * 272;
#pragma unroll
            for (int kk = 0; kk < 8; ++kk) {
                u32 a4[4];
                ldmA(a4, amt + kk * 32);
#pragma unroll
                for (int nt = 0; nt < 4; ++nt) {
                    u32 b[2];
                    ldmB(b, aLaneB + (u32)(nt * 8) * 272 + kk * 32);
                    mmaf16(D[nt], a4, b);
                }
            }

            u32 hoff = wrA + (u32)(mt * 16 + rowl) * 272;
            int gn = base + mt * 16 + rowl;
#pragma unroll
            for (int nt = 0; nt < 4; ++nt) {
                float s0 = __shfl_xor_sync(~0u, D[nt][0], 1);
                float s1 = __shfl_xor_sync(~0u, D[nt][1], 1);
                float s2 = __shfl_xor_sync(~0u, D[nt][2], 1);
                float s3 = __shfl_xor_sync(~0u, D[nt][3], 1);
                float vi, vf, vg, vo;
                if (codd == 0) { vi = D[nt][0]; vf = D[nt][1]; vg = s0; vo = s1; }
                else           { vi = s2;       vf = s3;       vg = D[nt][2]; vo = D[nt][3]; }
                float yi, yf, yg, yo;
                unpack_y(ycur[nt], yi, yf, yg, yo);
                vi += yi; vf += yf; vg += yg; vo += yo;
                int ci = mt * 4 + nt;
                float cc = sigt(vf) * cst[ci] + sigt(vi) * tanha(vg);
                cst[ci] = cc;
                float h = sigt(vo) * tanha(cc);
                __half bh = __float2half(h);
                asm volatile("st.shared.b16 [%0],%1;" :: "r"(hoff + (u32)(kgb + 2 * nt) * 2),
                             "h"(*(unsigned short*)&bh) : "memory");
                if (t == 15 && gn < NN) g_h[(size_t)gn * 128 + kgb + 2 * nt] = h;
            }
        }
    }
}

// ---- epilogue ----
__global__ __launch_bounds__(256, 1) void epi_kernel(
    const float* __restrict__ x, const float* __restrict__ b_self, const float* __restrict__ b_neigh,
    const float* __restrict__ g1, const float* __restrict__ bt1,
    const float* __restrict__ g3, const float* __restrict__ bt3, float* __restrict__ out) {
    extern __shared__ float smem[];
    float* ws = smem;
    float* wn = smem + 16384;
    float* sm_x = smem + 32768;
    float* sm_h = smem + 37120;
    float* sm_r = smem + 41472;
    const int tid = threadIdx.x, j = tid & 127, ng = tid >> 7, base = blockIdx.x * TN;

    cp_chunk(ws, g_WselfT, tid); cp_chunk(wn, g_WneighT, tid); cp_commit();
    stage_tile(sm_x, x, base, tid);
    stage_tile(sm_h, g_h, base, tid);
    cp_wait<0>();
    __syncthreads();

    float bsn = b_self[j] + b_neigh[j];
    u64 racc[8];
#pragma unroll
    for (int p = 0; p < 8; ++p) racc[p] = pack2s(bsn);
#pragma unroll 4
    for (int k = 0; k < 128; ++k) {
        u64 wsv = pack2s(ws[k * 128 + j]);
        u64 wnv = pack2s(wn[k * 128 + j]);
        const u64* xp = (const u64*)(sm_x + k * HSTR + ng * 16);
        const u64* hp = (const u64*)(sm_h + k * HSTR + ng * 16);
#pragma unroll
        for (int p = 0; p < 8; ++p) { ffma2(racc[p], wsv, xp[p]); ffma2(racc[p], wnv, hp[p]); }
    }
#pragma unroll
    for (int p = 0; p < 8; ++p) {
        float lo, hi; unpack2(racc[p], lo, hi);
        int node = ng * 16 + 2 * p;
        sm_r[node * 132 + j] = lo;
        sm_r[(node + 1) * 132 + j] = hi;
    }
    __syncthreads();

    int w = tid >> 5, l = tid & 31;
    float4 gv1 = *(const float4*)(g1 + l * 4), bv1 = *(const float4*)(bt1 + l * 4);
    float4 gv3 = *(const float4*)(g3 + l * 4), bv3 = *(const float4*)(bt3 + l * 4);
#pragma unroll 1
    for (int q = 0; q < 4; ++q) {
        int node = w * 4 + q, n = base + node;
        if (n >= NN) break;
        float4 rv = *(float4*)(sm_r + node * 132 + l * 4);
        float4 xv = *(const float4*)(x + (size_t)n * 128 + l * 4);
        float s1 = rv.x + rv.y + rv.z + rv.w;
        float s2 = rv.x * rv.x + rv.y * rv.y + rv.z * rv.z + rv.w * rv.w;
#pragma unroll
        for (int mm = 16; mm > 0; mm >>= 1) { s1 += __shfl_xor_sync(~0u, s1, mm); s2 += __shfl_xor_sync(~0u, s2, mm); }
        float mu = s1 * 0.0078125f;
        float rs = rsqrtf(s2 * 0.0078125f - mu * mu + 1e-5f);
        float4 h;
        h.x = (rv.x - mu) * rs * gv1.x + bv1.x; h.y = (rv.y - mu) * rs * gv1.y + bv1.y;
        h.z = (rv.z - mu) * rs * gv1.z + bv1.z; h.w = (rv.w - mu) * rs * gv1.w + bv1.w;
        h.x = fmaxf(h.x, 0.01f * h.x) + xv.x; h.y = fmaxf(h.y, 0.01f * h.y) + xv.y;
        h.z = fmaxf(h.z, 0.01f * h.z) + xv.z; h.w = fmaxf(h.w, 0.01f * h.w) + xv.w;
        s1 = h.x + h.y + h.z + h.w;
        s2 = h.x * h.x + h.y * h.y + h.z * h.z + h.w * h.w;
#pragma unroll
        for (int mm = 16; mm > 0; mm >>= 1) { s1 += __shfl_xor_sync(~0u, s1, mm); s2 += __shfl_xor_sync(~0u, s2, mm); }
        mu = s1 * 0.0078125f;
        rs = rsqrtf(s2 * 0.0078125f - mu * mu + 1e-5f);
        float4 o;
        o.x = (h.x - mu) * rs * gv3.x + bv3.x; o.y = (h.y - mu) * rs * gv3.y + bv3.y;
        o.z = (h.z - mu) * rs * gv3.z + bv3.z; o.w = (h.w - mu) * rs * gv3.w + bv3.w;
        o.x = fmaxf(o.x, 0.01f * o.x); o.y = fmaxf(o.y, 0.01f * o.y);
        o.z = fmaxf(o.z, 0.01f * o.z); o.w = fmaxf(o.w, 0.01f * o.w);
        *(float4*)(out + (size_t)n * 128 + l * 4) = o;
    }
}

extern "C" void kernel_launch(void* const* d_in, const int* in_sizes, int n_in,
                              void* d_out, int out_size) {
    const float* x       = (const float*)d_in[0];
    const int*   nidx    = (const int*)d_in[1];
    const float* W_self  = (const float*)d_in[2];
    const float* b_self  = (const float*)d_in[3];
    const float* W_neigh = (const float*)d_in[4];
    const float* b_neigh = (const float*)d_in[5];
    const float* W_ih    = (const float*)d_in[6];
    const float* W_hh    = (const float*)d_in[7];
    const float* b_ih    = (const float*)d_in[8];
    const float* b_hh    = (const float*)d_in[9];
    const float* g1      = (const float*)d_in[10];
    const float* bt1     = (const float*)d_in[11];
    const float* g3      = (const float*)d_in[12];
    const float* bt3     = (const float*)d_in[13];
    float* out = (float*)d_out;

    cudaFuncSetAttribute(y_kernel,   cudaFuncAttributeMaxDynamicSharedMemorySize, 148480);
    cudaFuncSetAttribute(lstm64,     cudaFuncAttributeMaxDynamicSharedMemorySize, LSTM_SMEM);
    cudaFuncSetAttribute(epi_kernel, cudaFuncAttributeMaxDynamicSharedMemorySize, 182784);

    int blk32 = (NN + TN - 1) / TN;        // 1563
    int blk64 = (NN + NODES - 1) / NODES;  // 782
    prep_kernel<<<256, 256>>>(W_ih, W_hh, W_self, W_neigh);
    y_kernel<<<blk32, 256, 148480>>>(x, b_ih, b_hh);
    lstm64<<<blk64, LTHREADS, LSTM_SMEM>>>(nidx);
    epi_kernel<<<blk32, 256, 182784>>>(x, b_self, b_neigh, g1, bt1, g3, bt3, out);
}

// round 10
// speedup vs baseline: 3.0814x; 1.1200x over previous
#include <cuda_runtime.h>
#include <cuda_fp16.h>

#define NN 50000
#define TN 32
typedef unsigned long long u64;
typedef unsigned int u32;

__device__ __align__(256) __half g_yh[(size_t)NN * 512];    // gate-interleaved fp16: [node][unit*4+type]
__device__ __align__(256) float g_h[(size_t)NN * 128];
__device__ __align__(256) float g_WihT[128 * 512];
__device__ __align__(256) float g_WselfT[128 * 128];
__device__ __align__(256) float g_WneighT[128 * 128];
__device__ __align__(256) __half g_Wp[512 * 136];           // permuted fp16 W_hh, 272B row stride

// ---- fp32x2 helpers ----
__device__ __forceinline__ u64 pack2(float lo, float hi) {
    u64 r; asm("mov.b64 %0,{%1,%2};" : "=l"(r) : "f"(lo), "f"(hi)); return r;
}
__device__ __forceinline__ u64 pack2s(float v) { return pack2(v, v); }
__device__ __forceinline__ void unpack2(u64 v, float& lo, float& hi) {
    asm("mov.b64 {%0,%1},%2;" : "=f"(lo), "=f"(hi) : "l"(v));
}
__device__ __forceinline__ void ffma2(u64& d, u64 a, u64 b) {
    asm("fma.rn.f32x2 %0,%1,%2,%0;" : "+l"(d) : "l"(a), "l"(b));
}
__device__ __forceinline__ void cp16(void* dst, const void* src) {
    unsigned sa = (unsigned)__cvta_generic_to_shared(dst);
    asm volatile("cp.async.cg.shared.global [%0],[%1],16;" :: "r"(sa), "l"(src) : "memory");
}
__device__ __forceinline__ void cp_commit() { asm volatile("cp.async.commit_group;" ::: "memory"); }
template <int W> __device__ __forceinline__ void cp_wait() {
    asm volatile("cp.async.wait_group %0;" :: "n"(W) : "memory");
}
__device__ __forceinline__ void cp_chunk(float* dstS, const float* src, int tid) {
#pragma unroll
    for (int i = 0; i < 16; ++i) { int f4 = i * 256 + tid; cp16(dstS + f4 * 4, src + f4 * 4); }
}
// ---- fast activations ----
__device__ __forceinline__ float tanha(float x) {
    float r; asm("tanh.approx.f32 %0,%1;" : "=f"(r) : "f"(x)); return r;
}
__device__ __forceinline__ float sigt(float x) { return fmaf(tanha(0.5f * x), 0.5f, 0.5f); }

// ---- tensor-core (legacy mma.sync, baseline sm_100) ----
__device__ __forceinline__ u32 smem_u32(const void* p) {
    u32 a; asm("{ .reg .u64 t; cvta.to.shared.u64 t,%1; cvt.u32.u64 %0,t; }" : "=r"(a) : "l"(p)); return a;
}
__device__ __forceinline__ void ldmA(u32* r, u32 a) {
    asm volatile("ldmatrix.sync.aligned.m8n8.x4.shared.b16 {%0,%1,%2,%3},[%4];"
        : "=r"(r[0]), "=r"(r[1]), "=r"(r[2]), "=r"(r[3]) : "r"(a));
}
__device__ __forceinline__ void ldmB(u32* r, u32 a) {
    asm volatile("ldmatrix.sync.aligned.m8n8.x2.shared.b16 {%0,%1},[%2];"
        : "=r"(r[0]), "=r"(r[1]) : "r"(a));
}
__device__ __forceinline__ void mmaf16(float* d, const u32* a, const u32* b) {
    asm volatile("mma.sync.aligned.m16n8k16.row.col.f32.f16.f16.f32 "
        "{%0,%1,%2,%3},{%4,%5,%6,%7},{%8,%9},{%0,%1,%2,%3};"
        : "+f"(d[0]), "+f"(d[1]), "+f"(d[2]), "+f"(d[3])
        : "r"(a[0]), "r"(a[1]), "r"(a[2]), "r"(a[3]), "r"(b[0]), "r"(b[1]));
}

// lstm smem (bytes): W[139264] | A: 2 bufs x 17408 (64 rows x 272B fp16) | sidx[4096]
#define W_OFF 0
#define A_OFF 139264
#define ABUF  17408
#define SIDX_OFF 174080
#define LSTM_SMEM 178176
#define NODES 64
#define LTHREADS 512

// ---- prep ----
__global__ void prep_kernel(const float* __restrict__ W_ih, const float* __restrict__ W_hh,
                            const float* __restrict__ W_self, const float* __restrict__ W_neigh) {
    int i = blockIdx.x * 256 + threadIdx.x;
    if (i < 512 * 128) {
        int g = i >> 7, k = i & 127;
        g_WihT[k * 512 + g] = W_ih[i];
        int type = g >> 7, u = g & 127;
        g_Wp[(((u << 2) | type) * 136) + k] = __float2half(W_hh[i]);
    }
    if (i < 128 * 128) {
        int jj = i & 127, k = i >> 7;
        g_WselfT[k * 128 + jj] = W_self[jj * 128 + k];
        g_WneighT[k * 128 + jj] = W_neigh[jj * 128 + k];
    }
}

#define HSTR 34
__device__ __forceinline__ void stage_tile(float* sm, const float* __restrict__ src, int base, int tid) {
    int node = tid >> 3, q = tid & 7, n = base + node;
#pragma unroll
    for (int u = 0; u < 4; ++u) {
        float4 v = make_float4(0.f, 0.f, 0.f, 0.f);
        if (n < NN) v = ((const float4*)(src + (size_t)n * 128))[q * 4 + u];
        int k0 = q * 16 + u * 4;
        sm[(k0 + 0) * HSTR + node] = v.x; sm[(k0 + 1) * HSTR + node] = v.y;
        sm[(k0 + 2) * HSTR + node] = v.z; sm[(k0 + 3) * HSTR + node] = v.w;
    }
}

// ---- y = x @ W_ih^T + b_ih + b_hh, stored gate-interleaved fp16 ----
__global__ __launch_bounds__(256, 1) void y_kernel(const float* __restrict__ x,
                                                   const float* __restrict__ b_ih,
                                                   const float* __restrict__ b_hh) {
    extern __shared__ float smem[];
    float* buf[2] = { smem, smem + 16384 };
    float* sm_x = smem + 32768;
    const int tid = threadIdx.x, j = tid & 127, ng = tid >> 7, base = blockIdx.x * TN;

    cp_chunk(buf[0], g_WihT, tid); cp_commit();
    stage_tile(sm_x, x, base, tid);

    float bi = b_ih[j] + b_hh[j], bf = b_ih[128 + j] + b_hh[128 + j];
    float bg = b_ih[256 + j] + b_hh[256 + j], bo = b_ih[384 + j] + b_hh[384 + j];
    u64 ai[8], af[8], ag[8], ao[8];
#pragma unroll
    for (int p = 0; p < 8; ++p) { ai[p] = pack2s(bi); af[p] = pack2s(bf); ag[p] = pack2s(bg); ao[p] = pack2s(bo); }

    int cur = 0;
#pragma unroll 1
    for (int kc = 0; kc < 4; ++kc) {
        __syncthreads();
        if (kc < 3) { cp_chunk(buf[cur ^ 1], g_WihT + (kc + 1) * 16384, tid); cp_commit(); cp_wait<1>(); }
        else cp_wait<0>();
        __syncthreads();
        const float* Wb = buf[cur];
        const float* act = sm_x + kc * 32 * HSTR + ng * 16;
#pragma unroll 8
        for (int kk = 0; kk < 32; ++kk) {
            const float* wr = Wb + kk * 512 + j;
            u64 wi = pack2s(wr[0]), wf = pack2s(wr[128]), wg = pack2s(wr[256]), wo = pack2s(wr[384]);
            const u64* hp = (const u64*)(act + kk * HSTR);
#pragma unroll
            for (int p = 0; p < 8; ++p) {
                u64 hv = hp[p];
                ffma2(ai[p], wi, hv); ffma2(af[p], wf, hv);
                ffma2(ag[p], wg, hv); ffma2(ao[p], wo, hv);
            }
        }
        cur ^= 1;
    }
#pragma unroll
    for (int p = 0; p < 8; ++p) {
        int n0 = base + ng * 16 + 2 * p, n1 = n0 + 1;
        float i0, i1, f0, f1, q0, q1, o0, o1;
        unpack2(ai[p], i0, i1); unpack2(af[p], f0, f1);
        unpack2(ag[p], q0, q1); unpack2(ao[p], o0, o1);
        if (n0 < NN) {
            __half2 a = __floats2half2_rn(i0, f0), b = __floats2half2_rn(q0, o0);
            u64 v = (u64)(*(u32*)&a) | ((u64)(*(u32*)&b) << 32);
            *(u64*)(g_yh + (size_t)n0 * 512 + 4 * j) = v;
        }
        if (n1 < NN) {
            __half2 a = __floats2half2_rn(i1, f1), b = __floats2half2_rn(q1, o1);
            u64 v = (u64)(*(u32*)&a) | ((u64)(*(u32*)&b) << 32);
            *(u64*)(g_yh + (size_t)n1 * 512 + 4 * j) = v;
        }
    }
}

__device__ __forceinline__ void unpack_y(u64 raw, float& vi, float& vf, float& vg, float& vo) {
    u32 w0 = (u32)raw, w1 = (u32)(raw >> 32);
    float2 p = __half22float2(*(__half2*)&w0);
    float2 q = __half22float2(*(__half2*)&w1);
    vi = p.x; vf = p.y; vg = q.x; vo = q.y;
}

// ---- LSTM: 64 nodes/CTA, 512 threads, W fragments register-resident ----
__global__ __launch_bounds__(LTHREADS, 1) void lstm64(const int* __restrict__ nidx) {
    extern __shared__ char sb[];
    u32 sbase = smem_u32(sb);
    const int tid = threadIdx.x, w = tid >> 5, lane = tid & 31;
    const int base = blockIdx.x * NODES;
    int* sidx = (int*)(sb + SIDX_OFF);

    // load permuted fp16 W_hh (139264 B = 8704 x 16B)
#pragma unroll
    for (int i = 0; i < 17; ++i) { int c16 = i * LTHREADS + tid; cp16(sb + c16 * 16, (const char*)g_Wp + c16 * 16); }
    cp_commit();
    for (int i = tid; i < NODES * 16; i += LTHREADS) {
        int n = base + (i >> 4);
        sidx[i] = (n < NN) ? nidx[n * 16 + (i & 15)] : 0;
    }

    const int g = lane >> 2, codd = lane & 1, chi = (lane >> 1) & 1;
    const int rowl = g + codd * 8;              // node row within m-tile
    const int kgb = w * 8 + chi;                // unit base; cell unit = kgb + 2*nt
    const u32 ybOff = (u32)(w * 32 + chi * 4);

    float cst[16];
#pragma unroll
    for (int i = 0; i < 16; ++i) cst[i] = 0.f;

    cp_wait<0>();
    __syncthreads();

    // ---- hoist ALL W (B) fragments into registers: constant for whole kernel ----
    u32 bfr[64];
    {
        const u32 aLaneB = sbase + W_OFF + (u32)(w * 32 + (lane & 7)) * 272 + (u32)((lane & 8) * 2);
#pragma unroll
        for (int kk = 0; kk < 8; ++kk)
#pragma unroll
            for (int nt = 0; nt < 4; ++nt)
                ldmB(&bfr[(kk * 4 + nt) * 2], aLaneB + (u32)(nt * 8) * 272 + (u32)(kk * 32));
    }

    // ---- t = 0: gates = y only ----
#pragma unroll 1
    for (int mt = 0; mt < 4; ++mt) {
        int rn = sidx[(mt * 16 + rowl) * 16];
        const __half* yb = g_yh + (size_t)rn * 512 + ybOff;
        u32 hoff = sbase + A_OFF + (u32)(mt * 16 + rowl) * 272;
#pragma unroll
        for (int nt = 0; nt < 4; ++nt) {
            float vi, vf, vg, vo;
            unpack_y(*(const u64*)(yb + nt * 8), vi, vf, vg, vo);
            float cc = sigt(vi) * tanha(vg);
            cst[mt * 4 + nt] = cc;
            float h = sigt(vo) * tanha(cc);
            __half bh = __float2half(h);
            asm volatile("st.shared.b16 [%0],%1;" :: "r"(hoff + (u32)(kgb + 2 * nt) * 2),
                         "h"(*(unsigned short*)&bh) : "memory");
        }
    }

    u64 ybufA[4], ybufB[4];
    {
        int rn = sidx[rowl * 16 + 1];
        const __half* yb = g_yh + (size_t)rn * 512 + ybOff;
#pragma unroll
        for (int j = 0; j < 4; ++j) ybufA[j] = *(const u64*)(yb + j * 8);
    }

    // ---- t = 1..15 ----
#pragma unroll 1
    for (int t = 1; t < 16; ++t) {
        __syncthreads();
        const u32 rdA = sbase + A_OFF + (u32)(((t - 1) & 1) * ABUF);
        const u32 wrA = sbase + A_OFF + (u32)((t & 1) * ABUF);
        const u32 aLaneA = rdA + (u32)(lane & 15) * 272 + (u32)(lane & 16);
#pragma unroll 1
        for (int mt = 0; mt < 4; ++mt) {
            u64* ycur = (mt & 1) ? ybufB : ybufA;
            u64* ynxt = (mt & 1) ? ybufA : ybufB;
            {
                int pmt = (mt < 3) ? (mt + 1) : 0;
                int pt = (mt < 3) ? t : (t + 1);
                if (pt < 16) {
                    int rn = sidx[(pmt * 16 + rowl) * 16 + pt];
                    const __half* yb = g_yh + (size_t)rn * 512 + ybOff;
#pragma unroll
                    for (int j = 0; j < 4; ++j) ynxt[j] = *(const u64*)(yb + j * 8);
                }
            }

            float D[4][4];
#pragma unroll
            for (int j = 0; j < 4; ++j) { D[j][0] = 0.f; D[j][1] = 0.f; D[j][2] = 0.f; D[j][3] = 0.f; }

            u32 amt = aLaneA + (u32)(mt * 16) * 272;
            u32 afr[2][4];
            ldmA(afr[0], amt);
#pragma unroll
            for (int kk = 0; kk < 8; ++kk) {
                if (kk < 7) ldmA(afr[(kk + 1) & 1], amt + (u32)((kk + 1) * 32));
#pragma unroll
                for (int nt = 0; nt < 4; ++nt)
                    mmaf16(D[nt], afr[kk & 1], &bfr[(kk * 4 + nt) * 2]);
            }

            u32 hoff = wrA + (u32)(mt * 16 + rowl) * 272;
            int gn = base + mt * 16 + rowl;
#pragma unroll
            for (int nt = 0; nt < 4; ++nt) {
                float s0 = __shfl_xor_sync(~0u, D[nt][0], 1);
                float s1 = __shfl_xor_sync(~0u, D[nt][1], 1);
                float s2 = __shfl_xor_sync(~0u, D[nt][2], 1);
                float s3 = __shfl_xor_sync(~0u, D[nt][3], 1);
                float vi, vf, vg, vo;
                if (codd == 0) { vi = D[nt][0]; vf = D[nt][1]; vg = s0; vo = s1; }
                else           { vi = s2;       vf = s3;       vg = D[nt][2]; vo = D[nt][3]; }
                float yi, yf, yg, yo;
                unpack_y(ycur[nt], yi, yf, yg, yo);
                vi += yi; vf += yf; vg += yg; vo += yo;
                int ci = mt * 4 + nt;
                float cc = sigt(vf) * cst[ci] + sigt(vi) * tanha(vg);
                cst[ci] = cc;
                float h = sigt(vo) * tanha(cc);
                __half bh = __float2half(h);
                asm volatile("st.shared.b16 [%0],%1;" :: "r"(hoff + (u32)(kgb + 2 * nt) * 2),
                             "h"(*(unsigned short*)&bh) : "memory");
                if (t == 15 && gn < NN) g_h[(size_t)gn * 128 + kgb + 2 * nt] = h;
            }
        }
    }
}

// ---- epilogue ----
__global__ __launch_bounds__(256, 1) void epi_kernel(
    const float* __restrict__ x, const float* __restrict__ b_self, const float* __restrict__ b_neigh,
    const float* __restrict__ g1, const float* __restrict__ bt1,
    const float* __restrict__ g3, const float* __restrict__ bt3, float* __restrict__ out) {
    extern __shared__ float smem[];
    float* ws = smem;
    float* wn = smem + 16384;
    float* sm_x = smem + 32768;
    float* sm_h = smem + 37120;
    float* sm_r = smem + 41472;
    const int tid = threadIdx.x, j = tid & 127, ng = tid >> 7, base = blockIdx.x * TN;

    cp_chunk(ws, g_WselfT, tid); cp_chunk(wn, g_WneighT, tid); cp_commit();
    stage_tile(sm_x, x, base, tid);
    stage_tile(sm_h, g_h, base, tid);
    cp_wait<0>();
    __syncthreads();

    float bsn = b_self[j] + b_neigh[j];
    u64 racc[8];
#pragma unroll
    for (int p = 0; p < 8; ++p) racc[p] = pack2s(bsn);
#pragma unroll 4
    for (int k = 0; k < 128; ++k) {
        u64 wsv = pack2s(ws[k * 128 + j]);
        u64 wnv = pack2s(wn[k * 128 + j]);
        const u64* xp = (const u64*)(sm_x + k * HSTR + ng * 16);
        const u64* hp = (const u64*)(sm_h + k * HSTR + ng * 16);
#pragma unroll
        for (int p = 0; p < 8; ++p) { ffma2(racc[p], wsv, xp[p]); ffma2(racc[p], wnv, hp[p]); }
    }
#pragma unroll
    for (int p = 0; p < 8; ++p) {
        float lo, hi; unpack2(racc[p], lo, hi);
        int node = ng * 16 + 2 * p;
        sm_r[node * 132 + j] = lo;
        sm_r[(node + 1) * 132 + j] = hi;
    }
    __syncthreads();

    int w = tid >> 5, l = tid & 31;
    float4 gv1 = *(const float4*)(g1 + l * 4), bv1 = *(const float4*)(bt1 + l * 4);
    float4 gv3 = *(const float4*)(g3 + l * 4), bv3 = *(const float4*)(bt3 + l * 4);
#pragma unroll 1
    for (int q = 0; q < 4; ++q) {
        int node = w * 4 + q, n = base + node;
        if (n >= NN) break;
        float4 rv = *(float4*)(sm_r + node * 132 + l * 4);
        float4 xv = *(const float4*)(x + (size_t)n * 128 + l * 4);
        float s1 = rv.x + rv.y + rv.z + rv.w;
        float s2 = rv.x * rv.x + rv.y * rv.y + rv.z * rv.z + rv.w * rv.w;
#pragma unroll
        for (int mm = 16; mm > 0; mm >>= 1) { s1 += __shfl_xor_sync(~0u, s1, mm); s2 += __shfl_xor_sync(~0u, s2, mm); }
        float mu = s1 * 0.0078125f;
        float rs = rsqrtf(s2 * 0.0078125f - mu * mu + 1e-5f);
        float4 h;
        h.x = (rv.x - mu) * rs * gv1.x + bv1.x; h.y = (rv.y - mu) * rs * gv1.y + bv1.y;
        h.z = (rv.z - mu) * rs * gv1.z + bv1.z; h.w = (rv.w - mu) * rs * gv1.w + bv1.w;
        h.x = fmaxf(h.x, 0.01f * h.x) + xv.x; h.y = fmaxf(h.y, 0.01f * h.y) + xv.y;
        h.z = fmaxf(h.z, 0.01f * h.z) + xv.z; h.w = fmaxf(h.w, 0.01f * h.w) + xv.w;
        s1 = h.x + h.y + h.z + h.w;
        s2 = h.x * h.x + h.y * h.y + h.z * h.z + h.w * h.w;
#pragma unroll
        for (int mm = 16; mm > 0; mm >>= 1) { s1 += __shfl_xor_sync(~0u, s1, mm); s2 += __shfl_xor_sync(~0u, s2, mm); }
        mu = s1 * 0.0078125f;
        rs = rsqrtf(s2 * 0.0078125f - mu * mu + 1e-5f);
        float4 o;
        o.x = (h.x - mu) * rs * gv3.x + bv3.x; o.y = (h.y - mu) * rs * gv3.y + bv3.y;
        o.z = (h.z - mu) * rs * gv3.z + bv3.z; o.w = (h.w - mu) * rs * gv3.w + bv3.w;
        o.x = fmaxf(o.x, 0.01f * o.x); o.y = fmaxf(o.y, 0.01f * o.y);
        o.z = fmaxf(o.z, 0.01f * o.z); o.w = fmaxf(o.w, 0.01f * o.w);
        *(float4*)(out + (size_t)n * 128 + l * 4) = o;
    }
}

extern "C" void kernel_launch(void* const* d_in, const int* in_sizes, int n_in,
                              void* d_out, int out_size) {
    const float* x       = (const float*)d_in[0];
    const int*   nidx    = (const int*)d_in[1];
    const float* W_self  = (const float*)d_in[2];
    const float* b_self  = (const float*)d_in[3];
    const float* W_neigh = (const float*)d_in[4];
    const float* b_neigh = (const float*)d_in[5];
    const float* W_ih    = (const float*)d_in[6];
    const float* W_hh    = (const float*)d_in[7];
    const float* b_ih    = (const float*)d_in[8];
    const float* b_hh    = (const float*)d_in[9];
    const float* g1      = (const float*)d_in[10];
    const float* bt1     = (const float*)d_in[11];
    const float* g3      = (const float*)d_in[12];
    const float* bt3     = (const float*)d_in[13];
    float* out = (float*)d_out;

    cudaFuncSetAttribute(y_kernel,   cudaFuncAttributeMaxDynamicSharedMemorySize, 148480);
    cudaFuncSetAttribute(lstm64,     cudaFuncAttributeMaxDynamicSharedMemorySize, LSTM_SMEM);
    cudaFuncSetAttribute(epi_kernel, cudaFuncAttributeMaxDynamicSharedMemorySize, 182784);

    int blk32 = (NN + TN - 1) / TN;        // 1563
    int blk64 = (NN + NODES - 1) / NODES;  // 782
    prep_kernel<<<256, 256>>>(W_ih, W_hh, W_self, W_neigh);
    y_kernel<<<blk32, 256, 148480>>>(x, b_ih, b_hh);
    lstm64<<<blk64, LTHREADS, LSTM_SMEM>>>(nidx);
    epi_kernel<<<blk32, 256, 182784>>>(x, b_self, b_neigh, g1, bt1, g3, bt3, out);
}

// round 11
// speedup vs baseline: 3.9559x; 1.2838x over previous
#include <cuda_runtime.h>
#include <cuda_fp16.h>

#define NN 50000
typedef unsigned long long u64;
typedef unsigned int u32;

__device__ __align__(256) __half g_yh[(size_t)NN * 512];   // gate-interleaved fp16: [node][unit*4+type]
__device__ __align__(256) float g_h[(size_t)NN * 128];
__device__ __align__(256) __half g_Wp[512 * 136];          // permuted fp16 W_hh, 272B row stride
__device__ __align__(256) __half g_Wihp[512 * 136];        // permuted fp16 W_ih, 272B row stride
__device__ __align__(256) __half g_Wc[128 * 264];          // [j][k0..255] = [W_self | W_neigh], 528B stride
__device__ __align__(256) float g_bp[512];                 // permuted b_ih+b_hh: [4u+type]
__device__ __align__(256) float g_bsn[128];                // b_self+b_neigh

// ---- async copy ----
__device__ __forceinline__ void cp16(void* dst, const void* src) {
    unsigned sa = (unsigned)__cvta_generic_to_shared(dst);
    asm volatile("cp.async.cg.shared.global [%0],[%1],16;" :: "r"(sa), "l"(src) : "memory");
}
__device__ __forceinline__ void cp_commit() { asm volatile("cp.async.commit_group;" ::: "memory"); }
template <int W> __device__ __forceinline__ void cp_wait() {
    asm volatile("cp.async.wait_group %0;" :: "n"(W) : "memory");
}
// ---- fast activations ----
__device__ __forceinline__ float tanha(float x) {
    float r; asm("tanh.approx.f32 %0,%1;" : "=f"(r) : "f"(x)); return r;
}
__device__ __forceinline__ float sigt(float x) { return fmaf(tanha(0.5f * x), 0.5f, 0.5f); }

// ---- tensor-core (legacy mma.sync, baseline sm_100) ----
__device__ __forceinline__ u32 smem_u32(const void* p) {
    u32 a; asm("{ .reg .u64 t; cvta.to.shared.u64 t,%1; cvt.u32.u64 %0,t; }" : "=r"(a) : "l"(p)); return a;
}
__device__ __forceinline__ void ldmA(u32* r, u32 a) {
    asm volatile("ldmatrix.sync.aligned.m8n8.x4.shared.b16 {%0,%1,%2,%3},[%4];"
        : "=r"(r[0]), "=r"(r[1]), "=r"(r[2]), "=r"(r[3]) : "r"(a));
}
__device__ __forceinline__ void ldmB(u32* r, u32 a) {
    asm volatile("ldmatrix.sync.aligned.m8n8.x2.shared.b16 {%0,%1},[%2];"
        : "=r"(r[0]), "=r"(r[1]) : "r"(a));
}
__device__ __forceinline__ void mmaf16(float* d, const u32* a, const u32* b) {
    asm volatile("mma.sync.aligned.m16n8k16.row.col.f32.f16.f16.f32 "
        "{%0,%1,%2,%3},{%4,%5,%6,%7},{%8,%9},{%0,%1,%2,%3};"
        : "+f"(d[0]), "+f"(d[1]), "+f"(d[2]), "+f"(d[3])
        : "r"(a[0]), "r"(a[1]), "r"(a[2]), "r"(a[3]), "r"(b[0]), "r"(b[1]));
}

// lstm smem (bytes): W[139264] | A: 2 bufs x 17408 | sidx[4096]
#define W_OFF 0
#define A_OFF 139264
#define ABUF  17408
#define SIDX_OFF 174080
#define LSTM_SMEM 178176
#define NODES 64
#define LTHREADS 512

// y2 smem: W[139264] | A x-tile [17408]
#define Y_A_OFF 139264
#define Y_SMEM  156672

// epi smem: B[67584] | A[33792] | R[33792]
#define EB_OFF 0
#define EA_OFF 67584
#define ER_OFF 101376
#define EPI_SMEM 135168

// ---- prep: permuted fp16 weights + folded biases ----
__global__ void prep_kernel(const float* __restrict__ W_ih, const float* __restrict__ W_hh,
                            const float* __restrict__ W_self, const float* __restrict__ W_neigh,
                            const float* __restrict__ b_ih, const float* __restrict__ b_hh,
                            const float* __restrict__ b_self, const float* __restrict__ b_neigh) {
    int i = blockIdx.x * 256 + threadIdx.x;
    if (i < 512 * 128) {
        int g = i >> 7, k = i & 127;
        int type = g >> 7, u = g & 127;
        int perm = ((u << 2) | type) * 136 + k;
        g_Wp[perm]   = __float2half(W_hh[i]);
        g_Wihp[perm] = __float2half(W_ih[i]);
    }
    if (i < 128 * 256) {
        int j = i >> 8, k = i & 255;
        g_Wc[j * 264 + k] = __float2half(k < 128 ? W_self[j * 128 + k] : W_neigh[j * 128 + (k - 128)]);
    }
    if (i < 512) {
        int type = i >> 7, u = i & 127;
        g_bp[(u << 2) | type] = b_ih[i] + b_hh[i];
    }
    if (i < 128) g_bsn[i] = b_self[i] + b_neigh[i];
}

// ---- y2: y = x @ W_ih^T + bias, via mma (one lstm-step-shaped GEMM per 64 nodes) ----
__global__ __launch_bounds__(LTHREADS, 1) void y2(const float* __restrict__ x) {
    extern __shared__ char sb[];
    u32 sbase = smem_u32(sb);
    const int tid = threadIdx.x, w = tid >> 5, lane = tid & 31;
    const int base = blockIdx.x * NODES;

#pragma unroll
    for (int i = 0; i < 17; ++i) { int c16 = i * LTHREADS + tid; cp16(sb + c16 * 16, (const char*)g_Wihp + c16 * 16); }
    cp_commit();

    // stage x -> fp16 A tile (row=node, 272B stride)
    {
        int r = tid >> 3, cq = tid & 7, n = base + r;
        const float4* s4 = (const float4*)(x + (size_t)n * 128 + cq * 16);
        u32 h2v[8];
#pragma unroll
        for (int u = 0; u < 4; ++u) {
            float4 v = make_float4(0.f, 0.f, 0.f, 0.f);
            if (n < NN) v = s4[u];
            __half2 a = __floats2half2_rn(v.x, v.y), b = __floats2half2_rn(v.z, v.w);
            h2v[u * 2] = *(u32*)&a; h2v[u * 2 + 1] = *(u32*)&b;
        }
        *(uint4*)(sb + Y_A_OFF + r * 272 + cq * 32)      = make_uint4(h2v[0], h2v[1], h2v[2], h2v[3]);
        *(uint4*)(sb + Y_A_OFF + r * 272 + cq * 32 + 16) = make_uint4(h2v[4], h2v[5], h2v[6], h2v[7]);
    }
    cp_wait<0>();
    __syncthreads();

    const int g = lane >> 2, codd = lane & 1, chi = (lane >> 1) & 1;
    const int rowl = g + codd * 8;
    const int kgb = w * 8 + chi;

    // hoist W_ih fragments
    u32 bfr[64];
    {
        const u32 aLaneB = sbase + (u32)(w * 32 + (lane & 7)) * 272 + (u32)((lane & 8) * 2);
#pragma unroll
        for (int kk = 0; kk < 8; ++kk)
#pragma unroll
            for (int nt = 0; nt < 4; ++nt)
                ldmB(&bfr[(kk * 4 + nt) * 2], aLaneB + (u32)(nt * 8) * 272 + (u32)(kk * 32));
    }

    const u32 aLaneA = sbase + Y_A_OFF + (u32)(lane & 15) * 272 + (u32)(lane & 16);
#pragma unroll 1
    for (int mt = 0; mt < 4; ++mt) {
        float D[4][4];
#pragma unroll
        for (int j = 0; j < 4; ++j) { D[j][0] = 0.f; D[j][1] = 0.f; D[j][2] = 0.f; D[j][3] = 0.f; }
        u32 amt = aLaneA + (u32)(mt * 16) * 272;
        u32 afr[2][4];
        ldmA(afr[0], amt);
#pragma unroll
        for (int kk = 0; kk < 8; ++kk) {
            if (kk < 7) ldmA(afr[(kk + 1) & 1], amt + (u32)((kk + 1) * 32));
#pragma unroll
            for (int nt = 0; nt < 4; ++nt)
                mmaf16(D[nt], afr[kk & 1], &bfr[(kk * 4 + nt) * 2]);
        }
        int gn = base + mt * 16 + rowl;
#pragma unroll
        for (int nt = 0; nt < 4; ++nt) {
            float s0 = __shfl_xor_sync(~0u, D[nt][0], 1);
            float s1 = __shfl_xor_sync(~0u, D[nt][1], 1);
            float s2 = __shfl_xor_sync(~0u, D[nt][2], 1);
            float s3 = __shfl_xor_sync(~0u, D[nt][3], 1);
            float vi, vf, vg, vo;
            if (codd == 0) { vi = D[nt][0]; vf = D[nt][1]; vg = s0; vo = s1; }
            else           { vi = s2;       vf = s3;       vg = D[nt][2]; vo = D[nt][3]; }
            int u = kgb + 2 * nt;
            float4 b4 = *(const float4*)(g_bp + 4 * u);
            vi += b4.x; vf += b4.y; vg += b4.z; vo += b4.w;
            __half2 pa = __floats2half2_rn(vi, vf), pb = __floats2half2_rn(vg, vo);
            u64 v = (u64)(*(u32*)&pa) | ((u64)(*(u32*)&pb) << 32);
            if (gn < NN) *(u64*)(g_yh + (size_t)gn * 512 + 4 * u) = v;
        }
    }
}

__device__ __forceinline__ void unpack_y(u64 raw, float& vi, float& vf, float& vg, float& vo) {
    u32 w0 = (u32)raw, w1 = (u32)(raw >> 32);
    float2 p = __half22float2(*(__half2*)&w0);
    float2 q = __half22float2(*(__half2*)&w1);
    vi = p.x; vf = p.y; vg = q.x; vo = q.y;
}

// ---- LSTM: 64 nodes/CTA, 512 threads, W fragments register-resident (unchanged core) ----
__global__ __launch_bounds__(LTHREADS, 1) void lstm64(const int* __restrict__ nidx) {
    extern __shared__ char sb[];
    u32 sbase = smem_u32(sb);
    const int tid = threadIdx.x, w = tid >> 5, lane = tid & 31;
    const int base = blockIdx.x * NODES;
    int* sidx = (int*)(sb + SIDX_OFF);

#pragma unroll
    for (int i = 0; i < 17; ++i) { int c16 = i * LTHREADS + tid; cp16(sb + c16 * 16, (const char*)g_Wp + c16 * 16); }
    cp_commit();
    for (int i = tid; i < NODES * 16; i += LTHREADS) {
        int n = base + (i >> 4);
        sidx[i] = (n < NN) ? nidx[n * 16 + (i & 15)] : 0;
    }

    const int g = lane >> 2, codd = lane & 1, chi = (lane >> 1) & 1;
    const int rowl = g + codd * 8;
    const int kgb = w * 8 + chi;
    const u32 ybOff = (u32)(w * 32 + chi * 4);

    float cst[16];
#pragma unroll
    for (int i = 0; i < 16; ++i) cst[i] = 0.f;

    cp_wait<0>();
    __syncthreads();

    u32 bfr[64];
    {
        const u32 aLaneB = sbase + W_OFF + (u32)(w * 32 + (lane & 7)) * 272 + (u32)((lane & 8) * 2);
#pragma unroll
        for (int kk = 0; kk < 8; ++kk)
#pragma unroll
            for (int nt = 0; nt < 4; ++nt)
                ldmB(&bfr[(kk * 4 + nt) * 2], aLaneB + (u32)(nt * 8) * 272 + (u32)(kk * 32));
    }

    // t = 0
#pragma unroll 1
    for (int mt = 0; mt < 4; ++mt) {
        int rn = sidx[(mt * 16 + rowl) * 16];
        const __half* yb = g_yh + (size_t)rn * 512 + ybOff;
        u32 hoff = sbase + A_OFF + (u32)(mt * 16 + rowl) * 272;
#pragma unroll
        for (int nt = 0; nt < 4; ++nt) {
            float vi, vf, vg, vo;
            unpack_y(*(const u64*)(yb + nt * 8), vi, vf, vg, vo);
            float cc = sigt(vi) * tanha(vg);
            cst[mt * 4 + nt] = cc;
            float h = sigt(vo) * tanha(cc);
            __half bh = __float2half(h);
            asm volatile("st.shared.b16 [%0],%1;" :: "r"(hoff + (u32)(kgb + 2 * nt) * 2),
                         "h"(*(unsigned short*)&bh) : "memory");
        }
    }

    u64 ybufA[4], ybufB[4];
    {
        int rn = sidx[rowl * 16 + 1];
        const __half* yb = g_yh + (size_t)rn * 512 + ybOff;
#pragma unroll
        for (int j = 0; j < 4; ++j) ybufA[j] = *(const u64*)(yb + j * 8);
    }

#pragma unroll 1
    for (int t = 1; t < 16; ++t) {
        __syncthreads();
        const u32 rdA = sbase + A_OFF + (u32)(((t - 1) & 1) * ABUF);
        const u32 wrA = sbase + A_OFF + (u32)((t & 1) * ABUF);
        const u32 aLaneA = rdA + (u32)(lane & 15) * 272 + (u32)(lane & 16);
#pragma unroll 1
        for (int mt = 0; mt < 4; ++mt) {
            u64* ycur = (mt & 1) ? ybufB : ybufA;
            u64* ynxt = (mt & 1) ? ybufA : ybufB;
            {
                int pmt = (mt < 3) ? (mt + 1) : 0;
                int pt = (mt < 3) ? t : (t + 1);
                if (pt < 16) {
                    int rn = sidx[(pmt * 16 + rowl) * 16 + pt];
                    const __half* yb = g_yh + (size_t)rn * 512 + ybOff;
#pragma unroll
                    for (int j = 0; j < 4; ++j) ynxt[j] = *(const u64*)(yb + j * 8);
                }
            }

            float D[4][4];
#pragma unroll
            for (int j = 0; j < 4; ++j) { D[j][0] = 0.f; D[j][1] = 0.f; D[j][2] = 0.f; D[j][3] = 0.f; }

            u32 amt = aLaneA + (u32)(mt * 16) * 272;
            u32 afr[2][4];
            ldmA(afr[0], amt);
#pragma unroll
            for (int kk = 0; kk < 8; ++kk) {
                if (kk < 7) ldmA(afr[(kk + 1) & 1], amt + (u32)((kk + 1) * 32));
#pragma unroll
                for (int nt = 0; nt < 4; ++nt)
                    mmaf16(D[nt], afr[kk & 1], &bfr[(kk * 4 + nt) * 2]);
            }

            u32 hoff = wrA + (u32)(mt * 16 + rowl) * 272;
            int gn = base + mt * 16 + rowl;
#pragma unroll
            for (int nt = 0; nt < 4; ++nt) {
                float s0 = __shfl_xor_sync(~0u, D[nt][0], 1);
                float s1 = __shfl_xor_sync(~0u, D[nt][1], 1);
                float s2 = __shfl_xor_sync(~0u, D[nt][2], 1);
                float s3 = __shfl_xor_sync(~0u, D[nt][3], 1);
                float vi, vf, vg, vo;
                if (codd == 0) { vi = D[nt][0]; vf = D[nt][1]; vg = s0; vo = s1; }
                else           { vi = s2;       vf = s3;       vg = D[nt][2]; vo = D[nt][3]; }
                float yi, yf, yg, yo;
                unpack_y(ycur[nt], yi, yf, yg, yo);
                vi += yi; vf += yf; vg += yg; vo += yo;
                int ci = mt * 4 + nt;
                float cc = sigt(vf) * cst[ci] + sigt(vi) * tanha(vg);
                cst[ci] = cc;
                float h = sigt(vo) * tanha(cc);
                __half bh = __float2half(h);
                asm volatile("st.shared.b16 [%0],%1;" :: "r"(hoff + (u32)(kgb + 2 * nt) * 2),
                             "h"(*(unsigned short*)&bh) : "memory");
                if (t == 15 && gn < NN) g_h[(size_t)gn * 128 + kgb + 2 * nt] = h;
            }
        }
    }
}

// ---- epi2: r = [x|h] @ [Ws|Wn]^T + bsn via mma, then LN->leaky->+x->LN->leaky ----
__global__ __launch_bounds__(256, 1) void epi2(
    const float* __restrict__ x,
    const float* __restrict__ g1, const float* __restrict__ bt1,
    const float* __restrict__ g3, const float* __restrict__ bt3, float* __restrict__ out) {
    extern __shared__ char sb[];
    u32 sbase = smem_u32(sb);
    const int tid = threadIdx.x, w = tid >> 5, lane = tid & 31;
    const int base = blockIdx.x * NODES;

    // load B = g_Wc (67584 B = 4224 x 16B)
#pragma unroll
    for (int i = 0; i < 17; ++i) {
        int c = i * 256 + tid;
        if (c < 4224) cp16(sb + EB_OFF + c * 16, (const char*)g_Wc + c * 16);
    }
    cp_commit();

    // stage A = [x fp16 | h fp16], row=node, 528B stride
    {
        int r = tid >> 2, cq = tid & 3, n = base + r;
        const float* src = (cq < 2) ? (x + (size_t)n * 128 + cq * 64)
                                    : (g_h + (size_t)n * 128 + (cq - 2) * 64);
        const float4* s4 = (const float4*)src;
#pragma unroll
        for (int u = 0; u < 8; ++u) {
            float4 a = make_float4(0.f, 0.f, 0.f, 0.f), b = a;
            if (n < NN) { a = s4[2 * u]; b = s4[2 * u + 1]; }
            __half2 h0 = __floats2half2_rn(a.x, a.y), h1 = __floats2half2_rn(a.z, a.w);
            __half2 h2 = __floats2half2_rn(b.x, b.y), h3 = __floats2half2_rn(b.z, b.w);
            *(uint4*)(sb + EA_OFF + r * 528 + cq * 128 + u * 16) =
                make_uint4(*(u32*)&h0, *(u32*)&h1, *(u32*)&h2, *(u32*)&h3);
        }
    }
    cp_wait<0>();
    __syncthreads();

    // GEMM: warp w -> m-tile (w&3), n-half (w>>2)
    const int mt = w & 3, nh = w >> 2;
    const u32 aLaneA = sbase + EA_OFF + (u32)((lane & 15) + mt * 16) * 528 + (u32)(lane & 16);
    float D[8][4];
#pragma unroll
    for (int j = 0; j < 8; ++j) { D[j][0] = 0.f; D[j][1] = 0.f; D[j][2] = 0.f; D[j][3] = 0.f; }
    u32 afr[2][4];
    ldmA(afr[0], aLaneA);
#pragma unroll
    for (int kk = 0; kk < 16; ++kk) {
        if (kk < 15) ldmA(afr[(kk + 1) & 1], aLaneA + (u32)((kk + 1) * 32));
#pragma unroll
        for (int nt = 0; nt < 8; ++nt) {
            u32 b2[2];
            ldmB(b2, sbase + EB_OFF + (u32)(nh * 64 + nt * 8 + (lane & 7)) * 528
                     + (u32)((lane & 8) * 2) + (u32)(kk * 32));
            mmaf16(D[nt], afr[kk & 1], b2);
        }
    }
    // store r (+bias) to sm_r
#pragma unroll
    for (int nt = 0; nt < 8; ++nt) {
        int c = nh * 64 + nt * 8 + (lane & 3) * 2;
        float2 bs = *(const float2*)(g_bsn + c);
        int r0 = mt * 16 + (lane >> 2);
        float2 p0 = make_float2(D[nt][0] + bs.x, D[nt][1] + bs.y);
        float2 p1 = make_float2(D[nt][2] + bs.x, D[nt][3] + bs.y);
        *(float2*)(sb + ER_OFF + r0 * 528 + c * 4) = p0;
        *(float2*)(sb + ER_OFF + (r0 + 8) * 528 + c * 4) = p1;
    }
    __syncthreads();

    // LN -> leaky -> +x -> LN -> leaky; warp w handles nodes w*8..w*8+7
    float* sm_r = (float*)(sb + ER_OFF);
    int l = lane;
    float4 gv1 = *(const float4*)(g1 + l * 4), bv1 = *(const float4*)(bt1 + l * 4);
    float4 gv3 = *(const float4*)(g3 + l * 4), bv3 = *(const float4*)(bt3 + l * 4);
#pragma unroll 1
    for (int q = 0; q < 8; ++q) {
        int node = w * 8 + q, n = base + node;
        if (n >= NN) break;
        float4 rv = *(float4*)(sm_r + node * 132 + l * 4);
        float4 xv = *(const float4*)(x + (size_t)n * 128 + l * 4);
        float s1 = rv.x + rv.y + rv.z + rv.w;
        float s2 = rv.x * rv.x + rv.y * rv.y + rv.z * rv.z + rv.w * rv.w;
#pragma unroll
        for (int mm = 16; mm > 0; mm >>= 1) { s1 += __shfl_xor_sync(~0u, s1, mm); s2 += __shfl_xor_sync(~0u, s2, mm); }
        float mu = s1 * 0.0078125f;
        float rs = rsqrtf(s2 * 0.0078125f - mu * mu + 1e-5f);
        float4 h;
        h.x = (rv.x - mu) * rs * gv1.x + bv1.x; h.y = (rv.y - mu) * rs * gv1.y + bv1.y;
        h.z = (rv.z - mu) * rs * gv1.z + bv1.z; h.w = (rv.w - mu) * rs * gv1.w + bv1.w;
        h.x = fmaxf(h.x, 0.01f * h.x) + xv.x; h.y = fmaxf(h.y, 0.01f * h.y) + xv.y;
        h.z = fmaxf(h.z, 0.01f * h.z) + xv.z; h.w = fmaxf(h.w, 0.01f * h.w) + xv.w;
        s1 = h.x + h.y + h.z + h.w;
        s2 = h.x * h.x + h.y * h.y + h.z * h.z + h.w * h.w;
#pragma unroll
        for (int mm = 16; mm > 0; mm >>= 1) { s1 += __shfl_xor_sync(~0u, s1, mm); s2 += __shfl_xor_sync(~0u, s2, mm); }
        mu = s1 * 0.0078125f;
        rs = rsqrtf(s2 * 0.0078125f - mu * mu + 1e-5f);
        float4 o;
        o.x = (h.x - mu) * rs * gv3.x + bv3.x; o.y = (h.y - mu) * rs * gv3.y + bv3.y;
        o.z = (h.z - mu) * rs * gv3.z + bv3.z; o.w = (h.w - mu) * rs * gv3.w + bv3.w;
        o.x = fmaxf(o.x, 0.01f * o.x); o.y = fmaxf(o.y, 0.01f * o.y);
        o.z = fmaxf(o.z, 0.01f * o.z); o.w = fmaxf(o.w, 0.01f * o.w);
        *(float4*)(out + (size_t)n * 128 + l * 4) = o;
    }
}

extern "C" void kernel_launch(void* const* d_in, const int* in_sizes, int n_in,
                              void* d_out, int out_size) {
    const float* x       = (const float*)d_in[0];
    const int*   nidx    = (const int*)d_in[1];
    const float* W_self  = (const float*)d_in[2];
    const float* b_self  = (const float*)d_in[3];
    const float* W_neigh = (const float*)d_in[4];
    const float* b_neigh = (const float*)d_in[5];
    const float* W_ih    = (const float*)d_in[6];
    const float* W_hh    = (const float*)d_in[7];
    const float* b_ih    = (const float*)d_in[8];
    const float* b_hh    = (const float*)d_in[9];
    const float* g1      = (const float*)d_in[10];
    const float* bt1     = (const float*)d_in[11];
    const float* g3      = (const float*)d_in[12];
    const float* bt3     = (const float*)d_in[13];
    float* out = (float*)d_out;

    cudaFuncSetAttribute(y2,      cudaFuncAttributeMaxDynamicSharedMemorySize, Y_SMEM);
    cudaFuncSetAttribute(lstm64,  cudaFuncAttributeMaxDynamicSharedMemorySize, LSTM_SMEM);
    cudaFuncSetAttribute(epi2,    cudaFuncAttributeMaxDynamicSharedMemorySize, EPI_SMEM);

    int blk64 = (NN + NODES - 1) / NODES;  // 782
    prep_kernel<<<256, 256>>>(W_ih, W_hh, W_self, W_neigh, b_ih, b_hh, b_self, b_neigh);
    y2<<<blk64, LTHREADS, Y_SMEM>>>(x);
    lstm64<<<blk64, LTHREADS, LSTM_SMEM>>>(nidx);
    epi2<<<blk64, 256, EPI_SMEM>>>(x, g1, bt1, g3, bt3, out);
}

// round 12
// speedup vs baseline: 5.0900x; 1.2867x over previous
#include <cuda_runtime.h>
#include <cuda_fp16.h>

#define NN 50000
typedef unsigned long long u64;
typedef unsigned int u32;

__device__ __align__(256) __half g_yh[(size_t)NN * 512];   // gate quads: [node][4u+t]
__device__ __align__(256) __half g_Wp[512 * 136];          // W_hh, no-shuffle perm, 272B stride
__device__ __align__(256) __half g_Wihp[512 * 136];        // W_ih, same perm
__device__ __align__(256) __half g_Wc[128 * 264];          // [j][ W_self(128) | W_neigh(128) ], 528B stride
__device__ __align__(256) float g_bp[512];                 // b_ih+b_hh, quad layout [4u+t]
__device__ __align__(256) float g_bsn[128];                // b_self+b_neigh

// ---- async copy ----
__device__ __forceinline__ void cp16(void* dst, const void* src) {
    unsigned sa = (unsigned)__cvta_generic_to_shared(dst);
    asm volatile("cp.async.cg.shared.global [%0],[%1],16;" :: "r"(sa), "l"(src) : "memory");
}
__device__ __forceinline__ void cp_commit() { asm volatile("cp.async.commit_group;" ::: "memory"); }
template <int W> __device__ __forceinline__ void cp_wait() {
    asm volatile("cp.async.wait_group %0;" :: "n"(W) : "memory");
}
// ---- fast activations ----
__device__ __forceinline__ float tanha(float x) {
    float r; asm("tanh.approx.f32 %0,%1;" : "=f"(r) : "f"(x)); return r;
}
__device__ __forceinline__ float sigt(float x) { return fmaf(tanha(0.5f * x), 0.5f, 0.5f); }

// ---- tensor-core (legacy mma.sync, baseline sm_100) ----
__device__ __forceinline__ u32 smem_u32(const void* p) {
    u32 a; asm("{ .reg .u64 t; cvta.to.shared.u64 t,%1; cvt.u32.u64 %0,t; }" : "=r"(a) : "l"(p)); return a;
}
__device__ __forceinline__ void ldmA(u32* r, u32 a) {
    asm volatile("ldmatrix.sync.aligned.m8n8.x4.shared.b16 {%0,%1,%2,%3},[%4];"
        : "=r"(r[0]), "=r"(r[1]), "=r"(r[2]), "=r"(r[3]) : "r"(a));
}
__device__ __forceinline__ void ldmB(u32* r, u32 a) {
    asm volatile("ldmatrix.sync.aligned.m8n8.x2.shared.b16 {%0,%1},[%2];"
        : "=r"(r[0]), "=r"(r[1]) : "r"(a));
}
__device__ __forceinline__ void mmaf16(float* d, const u32* a, const u32* b) {
    asm volatile("mma.sync.aligned.m16n8k16.row.col.f32.f16.f16.f32 "
        "{%0,%1,%2,%3},{%4,%5,%6,%7},{%8,%9},{%0,%1,%2,%3};"
        : "+f"(d[0]), "+f"(d[1]), "+f"(d[2]), "+f"(d[3])
        : "r"(a[0]), "r"(a[1]), "r"(a[2]), "r"(a[3]), "r"(b[0]), "r"(b[1]));
}

// fused smem (bytes): W region [139264] (reused: Wc[67584] | x[17408] | r[33792]) | A 2x17408 | sidx[4096]
#define WC_OFF 0
#define X_OFF  67584
#define R_OFF  84992
#define A_OFF  139264
#define ABUF   17408
#define SIDX_OFF 174080
#define LSTM_SMEM 178176
#define NODES 64
#define LTHREADS 512
// y2 smem: W[139264] | A x-tile [17408]
#define Y_A_OFF 139264
#define Y_SMEM  156672

// no-shuffle gate column permutation: unit u, type t -> column
__device__ __forceinline__ int gate_col(int u, int t) {
    return ((u >> 3) << 5) + (((((t >> 1) << 1) | ((u >> 2) & 1))) << 3) + ((u & 3) << 1) + (t & 1);
}

// ---- prep ----
__global__ void prep_kernel(const float* __restrict__ W_ih, const float* __restrict__ W_hh,
                            const float* __restrict__ W_self, const float* __restrict__ W_neigh,
                            const float* __restrict__ b_ih, const float* __restrict__ b_hh,
                            const float* __restrict__ b_self, const float* __restrict__ b_neigh) {
    int i = blockIdx.x * 256 + threadIdx.x;
    if (i < 512 * 128) {
        int g = i >> 7, k = i & 127;
        int t = g >> 7, u = g & 127;
        int nc = gate_col(u, t);
        g_Wp[nc * 136 + k]   = __float2half(W_hh[i]);
        g_Wihp[nc * 136 + k] = __float2half(W_ih[i]);
    }
    if (i < 128 * 256) {
        int j = i >> 8, k = i & 255;
        g_Wc[j * 264 + k] = __float2half(k < 128 ? W_self[j * 128 + k] : W_neigh[j * 128 + (k - 128)]);
    }
    if (i < 512) {
        int t = i >> 7, u = i & 127;
        g_bp[(u << 2) | t] = b_ih[i] + b_hh[i];
    }
    if (i < 128) g_bsn[i] = b_self[i] + b_neigh[i];
}

// stage 64 fp32 rows -> fp16 A tile, 272B stride (512 threads)
__device__ __forceinline__ void stage_x16(char* sb, int off, const float* __restrict__ x, int base, int tid) {
    int r = tid >> 3, cq = tid & 7, n = base + r;
    const float4* s4 = (const float4*)(x + (size_t)n * 128 + cq * 16);
    u32 h2v[8];
#pragma unroll
    for (int u = 0; u < 4; ++u) {
        float4 v = make_float4(0.f, 0.f, 0.f, 0.f);
        if (n < NN) v = s4[u];
        __half2 a = __floats2half2_rn(v.x, v.y), b = __floats2half2_rn(v.z, v.w);
        h2v[u * 2] = *(u32*)&a; h2v[u * 2 + 1] = *(u32*)&b;
    }
    *(uint4*)(sb + off + r * 272 + cq * 32)      = make_uint4(h2v[0], h2v[1], h2v[2], h2v[3]);
    *(uint4*)(sb + off + r * 272 + cq * 32 + 16) = make_uint4(h2v[4], h2v[5], h2v[6], h2v[7]);
}

// ---- y2: y = x @ W_ih^T + bias (mma, shuffle-free decode) ----
__global__ __launch_bounds__(LTHREADS, 1) void y2(const float* __restrict__ x) {
    extern __shared__ char sb[];
    u32 sbase = smem_u32(sb);
    const int tid = threadIdx.x, w = tid >> 5, lane = tid & 31;
    const int base = blockIdx.x * NODES;

#pragma unroll
    for (int i = 0; i < 17; ++i) { int c16 = i * LTHREADS + tid; cp16(sb + c16 * 16, (const char*)g_Wihp + c16 * 16); }
    cp_commit();
    stage_x16(sb, Y_A_OFF, x, base, tid);
    cp_wait<0>();
    __syncthreads();

    const int q = lane & 3, r = lane >> 2;

    u32 bfr[64];
    {
        const u32 aLaneB = sbase + (u32)(w * 32 + (lane & 7)) * 272 + (u32)((lane & 8) * 2);
#pragma unroll
        for (int kk = 0; kk < 8; ++kk)
#pragma unroll
            for (int nt = 0; nt < 4; ++nt)
                ldmB(&bfr[(kk * 4 + nt) * 2], aLaneB + (u32)(nt * 8) * 272 + (u32)(kk * 32));
    }

    const u32 aLaneA = sbase + Y_A_OFF + (u32)(lane & 15) * 272 + (u32)(lane & 16);
#pragma unroll 1
    for (int mt = 0; mt < 4; ++mt) {
        float D[4][4];
#pragma unroll
        for (int j = 0; j < 4; ++j) { D[j][0] = 0.f; D[j][1] = 0.f; D[j][2] = 0.f; D[j][3] = 0.f; }
        u32 amt = aLaneA + (u32)(mt * 16) * 272;
        u32 afr[2][4];
        ldmA(afr[0], amt);
#pragma unroll
        for (int kk = 0; kk < 8; ++kk) {
            if (kk < 7) ldmA(afr[(kk + 1) & 1], amt + (u32)((kk + 1) * 32));
#pragma unroll
            for (int nt = 0; nt < 4; ++nt)
                mmaf16(D[nt], afr[kk & 1], &bfr[(kk * 4 + nt) * 2]);
        }
#pragma unroll
        for (int p = 0; p < 2; ++p)
#pragma unroll
            for (int rs = 0; rs < 2; ++rs) {
                int u = w * 8 + p * 4 + q;
                float vi = D[p][rs * 2] , vf = D[p][rs * 2 + 1];
                float vg = D[2 + p][rs * 2], vo = D[2 + p][rs * 2 + 1];
                float4 b4 = *(const float4*)(g_bp + 4 * u);
                vi += b4.x; vf += b4.y; vg += b4.z; vo += b4.w;
                int gn = base + mt * 16 + r + rs * 8;
                __half2 pa = __floats2half2_rn(vi, vf), pb = __floats2half2_rn(vg, vo);
                u64 v = (u64)(*(u32*)&pa) | ((u64)(*(u32*)&pb) << 32);
                if (gn < NN) *(u64*)(g_yh + (size_t)gn * 512 + 4 * u) = v;
            }
    }
}

__device__ __forceinline__ void unpack_y(u64 raw, float& vi, float& vf, float& vg, float& vo) {
    u32 w0 = (u32)raw, w1 = (u32)(raw >> 32);
    float2 p = __half22float2(*(__half2*)&w0);
    float2 q = __half22float2(*(__half2*)&w1);
    vi = p.x; vf = p.y; vg = q.x; vo = q.y;
}

// ---- fused LSTM + epilogue ----
__global__ __launch_bounds__(LTHREADS, 1) void lstm_epi(
    const int* __restrict__ nidx, const float* __restrict__ x,
    const float* __restrict__ g1, const float* __restrict__ bt1,
    const float* __restrict__ g3, const float* __restrict__ bt3, float* __restrict__ out) {
    extern __shared__ char sb[];
    u32 sbase = smem_u32(sb);
    const int tid = threadIdx.x, w = tid >> 5, lane = tid & 31;
    const int base = blockIdx.x * NODES;
    int* sidx = (int*)(sb + SIDX_OFF);

#pragma unroll
    for (int i = 0; i < 17; ++i) { int c16 = i * LTHREADS + tid; cp16(sb + c16 * 16, (const char*)g_Wp + c16 * 16); }
    cp_commit();
    for (int i = tid; i < NODES * 16; i += LTHREADS) {
        int n = base + (i >> 4);
        sidx[i] = (n < NN) ? nidx[n * 16 + (i & 15)] : 0;
    }

    const int q = lane & 3, r = lane >> 2;
    const int ubase = w * 8 + q;                       // + p*4
    float cst[16];
#pragma unroll
    for (int i = 0; i < 16; ++i) cst[i] = 0.f;

    cp_wait<0>();
    __syncthreads();

    // hoist W_hh fragments (W smem region dead afterwards)
    u32 bfr[64];
    {
        const u32 aLaneB = sbase + (u32)(w * 32 + (lane & 7)) * 272 + (u32)((lane & 8) * 2);
#pragma unroll
        for (int kk = 0; kk < 8; ++kk)
#pragma unroll
            for (int nt = 0; nt < 4; ++nt)
                ldmB(&bfr[(kk * 4 + nt) * 2], aLaneB + (u32)(nt * 8) * 272 + (u32)(kk * 32));
    }
    __syncthreads();  // all warps done reading W smem

    // overlap with t-loop: load Wc + stage x into dead W region
#pragma unroll
    for (int i = 0; i < 9; ++i) {
        int c = i * LTHREADS + tid;
        if (c < 4224) cp16(sb + WC_OFF + c * 16, (const char*)g_Wc + c * 16);
    }
    cp_commit();
    stage_x16(sb, X_OFF, x, base, tid);

    // ---- t = 0: gates = y only ----
#pragma unroll 1
    for (int mt = 0; mt < 4; ++mt) {
#pragma unroll
        for (int p = 0; p < 2; ++p)
#pragma unroll
            for (int rs = 0; rs < 2; ++rs) {
                int u = ubase + p * 4;
                int row = mt * 16 + r + rs * 8;
                int rn = sidx[row * 16];
                float vi, vf, vg, vo;
                unpack_y(*(const u64*)(g_yh + (size_t)rn * 512 + 4 * u), vi, vf, vg, vo);
                float cc = sigt(vi) * tanha(vg);
                cst[mt * 4 + p * 2 + rs] = cc;
                float h = sigt(vo) * tanha(cc);
                __half bh = __float2half(h);
                asm volatile("st.shared.b16 [%0],%1;" :: "r"(sbase + A_OFF + (u32)row * 272 + (u32)u * 2),
                             "h"(*(unsigned short*)&bh) : "memory");
            }
    }

    u64 ybufA[4], ybufB[4];
#pragma unroll
    for (int p = 0; p < 2; ++p)
#pragma unroll
        for (int rs = 0; rs < 2; ++rs) {
            int rn = sidx[(r + rs * 8) * 16 + 1];
            ybufA[p * 2 + rs] = *(const u64*)(g_yh + (size_t)rn * 512 + 4 * (ubase + p * 4));
        }

    // ---- t = 1..15 ----
#pragma unroll 1
    for (int t = 1; t < 16; ++t) {
        __syncthreads();
        const u32 rdA = sbase + A_OFF + (u32)(((t - 1) & 1) * ABUF);
        const u32 wrA = sbase + A_OFF + (u32)((t & 1) * ABUF);
        const u32 aLaneA = rdA + (u32)(lane & 15) * 272 + (u32)(lane & 16);
#pragma unroll 1
        for (int mt = 0; mt < 4; ++mt) {
            u64* ycur = (mt & 1) ? ybufB : ybufA;
            u64* ynxt = (mt & 1) ? ybufA : ybufB;
            {
                int pmt = (mt < 3) ? (mt + 1) : 0;
                int pt = (mt < 3) ? t : (t + 1);
                if (pt < 16) {
#pragma unroll
                    for (int p = 0; p < 2; ++p)
#pragma unroll
                        for (int rs = 0; rs < 2; ++rs) {
                            int rn = sidx[(pmt * 16 + r + rs * 8) * 16 + pt];
                            ynxt[p * 2 + rs] = *(const u64*)(g_yh + (size_t)rn * 512 + 4 * (ubase + p * 4));
                        }
                }
            }

            float D[4][4];
#pragma unroll
            for (int j = 0; j < 4; ++j) { D[j][0] = 0.f; D[j][1] = 0.f; D[j][2] = 0.f; D[j][3] = 0.f; }

            u32 amt = aLaneA + (u32)(mt * 16) * 272;
            u32 afr[2][4];
            ldmA(afr[0], amt);
#pragma unroll
            for (int kk = 0; kk < 8; ++kk) {
                if (kk < 7) ldmA(afr[(kk + 1) & 1], amt + (u32)((kk + 1) * 32));
#pragma unroll
                for (int nt = 0; nt < 4; ++nt)
                    mmaf16(D[nt], afr[kk & 1], &bfr[(kk * 4 + nt) * 2]);
            }

#pragma unroll
            for (int p = 0; p < 2; ++p)
#pragma unroll
                for (int rs = 0; rs < 2; ++rs) {
                    float vi = D[p][rs * 2], vf = D[p][rs * 2 + 1];
                    float vg = D[2 + p][rs * 2], vo = D[2 + p][rs * 2 + 1];
                    float yi, yf, yg, yo;
                    unpack_y(ycur[p * 2 + rs], yi, yf, yg, yo);
                    vi += yi; vf += yf; vg += yg; vo += yo;
                    int ci = mt * 4 + p * 2 + rs;
                    float cc = sigt(vf) * cst[ci] + sigt(vi) * tanha(vg);
                    cst[ci] = cc;
                    float h = sigt(vo) * tanha(cc);
                    int row = mt * 16 + r + rs * 8;
                    __half bh = __float2half(h);
                    asm volatile("st.shared.b16 [%0],%1;" :: "r"(wrA + (u32)row * 272 + (u32)(ubase + p * 4) * 2),
                                 "h"(*(unsigned short*)&bh) : "memory");
                }
        }
    }
    cp_wait<0>();
    __syncthreads();   // final h visible (A buf 1), Wc + x staged

    // ---- epilogue GEMM: r = x@Ws^T + h@Wn^T + bsn ----
    const int mt = w & 3, nc = w >> 2;
    const u32 hA = sbase + A_OFF + ABUF;   // t=15 wrote buf 1
    float D[4][4];
#pragma unroll
    for (int j = 0; j < 4; ++j) { D[j][0] = 0.f; D[j][1] = 0.f; D[j][2] = 0.f; D[j][3] = 0.f; }
#pragma unroll 1
    for (int pass = 0; pass < 2; ++pass) {
        const u32 aLaneA = (pass ? hA : (sbase + X_OFF)) + (u32)((lane & 15) + mt * 16) * 272 + (u32)(lane & 16);
        u32 afr[2][4];
        ldmA(afr[0], aLaneA);
#pragma unroll
        for (int kk = 0; kk < 8; ++kk) {
            if (kk < 7) ldmA(afr[(kk + 1) & 1], aLaneA + (u32)((kk + 1) * 32));
#pragma unroll
            for (int nt = 0; nt < 4; ++nt) {
                u32 b2[2];
                ldmB(b2, sbase + WC_OFF + (u32)(nc * 32 + nt * 8 + (lane & 7)) * 528
                         + (u32)(pass * 256) + (u32)((lane & 8) * 2) + (u32)(kk * 32));
                mmaf16(D[nt], afr[kk & 1], b2);
            }
        }
    }
#pragma unroll
    for (int nt = 0; nt < 4; ++nt) {
        int c = nc * 32 + nt * 8 + (lane & 3) * 2;
        float2 bs = *(const float2*)(g_bsn + c);
        int r0 = mt * 16 + (lane >> 2);
        *(float2*)(sb + R_OFF + r0 * 528 + c * 4) = make_float2(D[nt][0] + bs.x, D[nt][1] + bs.y);
        *(float2*)(sb + R_OFF + (r0 + 8) * 528 + c * 4) = make_float2(D[nt][2] + bs.x, D[nt][3] + bs.y);
    }
    __syncthreads();

    // ---- LN -> leaky -> +x -> LN -> leaky; warp w: nodes w*4..w*4+3 ----
    float* sm_r = (float*)(sb + R_OFF);
    float4 gv1 = *(const float4*)(g1 + lane * 4), bv1 = *(const float4*)(bt1 + lane * 4);
    float4 gv3 = *(const float4*)(g3 + lane * 4), bv3 = *(const float4*)(bt3 + lane * 4);
#pragma unroll 1
    for (int qq = 0; qq < 4; ++qq) {
        int node = w * 4 + qq, n = base + node;
        if (n >= NN) break;
        float4 rv = *(float4*)(sm_r + node * 132 + lane * 4);
        float4 xv = *(const float4*)(x + (size_t)n * 128 + lane * 4);
        float s1 = rv.x + rv.y + rv.z + rv.w;
        float s2 = rv.x * rv.x + rv.y * rv.y + rv.z * rv.z + rv.w * rv.w;
#pragma unroll
        for (int mm = 16; mm > 0; mm >>= 1) { s1 += __shfl_xor_sync(~0u, s1, mm); s2 += __shfl_xor_sync(~0u, s2, mm); }
        float mu = s1 * 0.0078125f;
        float rs = rsqrtf(s2 * 0.0078125f - mu * mu + 1e-5f);
        float4 h;
        h.x = (rv.x - mu) * rs * gv1.x + bv1.x; h.y = (rv.y - mu) * rs * gv1.y + bv1.y;
        h.z = (rv.z - mu) * rs * gv1.z + bv1.z; h.w = (rv.w - mu) * rs * gv1.w + bv1.w;
        h.x = fmaxf(h.x, 0.01f * h.x) + xv.x; h.y = fmaxf(h.y, 0.01f * h.y) + xv.y;
        h.z = fmaxf(h.z, 0.01f * h.z) + xv.z; h.w = fmaxf(h.w, 0.01f * h.w) + xv.w;
        s1 = h.x + h.y + h.z + h.w;
        s2 = h.x * h.x + h.y * h.y + h.z * h.z + h.w * h.w;
#pragma unroll
        for (int mm = 16; mm > 0; mm >>= 1) { s1 += __shfl_xor_sync(~0u, s1, mm); s2 += __shfl_xor_sync(~0u, s2, mm); }
        mu = s1 * 0.0078125f;
        rs = rsqrtf(s2 * 0.0078125f - mu * mu + 1e-5f);
        float4 o;
        o.x = (h.x - mu) * rs * gv3.x + bv3.x; o.y = (h.y - mu) * rs * gv3.y + bv3.y;
        o.z = (h.z - mu) * rs * gv3.z + bv3.z; o.w = (h.w - mu) * rs * gv3.w + bv3.w;
        o.x = fmaxf(o.x, 0.01f * o.x); o.y = fmaxf(o.y, 0.01f * o.y);
        o.z = fmaxf(o.z, 0.01f * o.z); o.w = fmaxf(o.w, 0.01f * o.w);
        *(float4*)(out + (size_t)n * 128 + lane * 4) = o;
    }
}

extern "C" void kernel_launch(void* const* d_in, const int* in_sizes, int n_in,
                              void* d_out, int out_size) {
    const float* x       = (const float*)d_in[0];
    const int*   nidx    = (const int*)d_in[1];
    const float* W_self  = (const float*)d_in[2];
    const float* b_self  = (const float*)d_in[3];
    const float* W_neigh = (const float*)d_in[4];
    const float* b_neigh = (const float*)d_in[5];
    const float* W_ih    = (const float*)d_in[6];
    const float* W_hh    = (const float*)d_in[7];
    const float* b_ih    = (const float*)d_in[8];
    const float* b_hh    = (const float*)d_in[9];
    const float* g1      = (const float*)d_in[10];
    const float* bt1     = (const float*)d_in[11];
    const float* g3      = (const float*)d_in[12];
    const float* bt3     = (const float*)d_in[13];
    float* out = (float*)d_out;

    cudaFuncSetAttribute(y2,       cudaFuncAttributeMaxDynamicSharedMemorySize, Y_SMEM);
    cudaFuncSetAttribute(lstm_epi, cudaFuncAttributeMaxDynamicSharedMemorySize, LSTM_SMEM);

    int blk64 = (NN + NODES - 1) / NODES;  // 782
    prep_kernel<<<256, 256>>>(W_ih, W_hh, W_self, W_neigh, b_ih, b_hh, b_self, b_neigh);
    y2<<<blk64, LTHREADS, Y_SMEM>>>(x);
    lstm_epi<<<blk64, LTHREADS, LSTM_SMEM>>>(nidx, x, g1, bt1, g3, bt3, out);
}